// round 3
// baseline (speedup 1.0000x reference)
#include <cuda_runtime.h>
#include <cstdint>
#include <math.h>

// ---------------- problem constants ----------------
#define BATCH 4
#define CIN   256
#define HH    128
#define WW    128
#define NANCH 9
#define NPIX  (HH*WW)         // 16384
#define NSC   (NPIX*NANCH)    // 147456 per image
#define PRE_K 600
#define POST_K 100
#define NMS_T 0.7f
#define MASKW 19              // ceil(600/32)

// ---------------- device scratch (static; no allocations) ----------------
__device__ __align__(16) float g_t[(size_t)BATCH*NPIX*CIN];   // conv out NHWC [b,y,x,oc]
__device__ __align__(16) float g_wT[9*CIN*CIN];               // [tap][ci][oc]
__device__ __align__(16) float g_hw[CIN*48];                  // [ci][48]: 9 cls + 36 bbox + 3 pad
__device__ float g_hb[48];
__device__ __align__(16) float g_anch[NANCH*4];
__device__ float g_scores[BATCH*NSC];
__device__ __align__(16) float g_deltas[(size_t)BATCH*NSC*4];
__device__ unsigned g_topidx[BATCH*PRE_K];
__device__ __align__(16) float g_boxes[BATCH*PRE_K*4];
__device__ unsigned g_mask[BATCH*PRE_K*MASKW];

__device__ __forceinline__ unsigned okey(float f) {
    unsigned u = __float_as_uint(f);
    return (u & 0x80000000u) ? ~u : (u | 0x80000000u);   // monotone float->uint
}

__device__ __forceinline__ float dimval(const int* p) {
    int raw = *p;
    if (raw > 0 && raw < 1000000) return (float)raw;     // stored as int32
    return __int_as_float(raw);                          // stored as float32
}

// ---------------- prep: weight transposes, head pack, anchors ----------------
__global__ void prep_kernel(const float* __restrict__ cw,
                            const float* __restrict__ clw, const float* __restrict__ clb,
                            const float* __restrict__ bw,  const float* __restrict__ bb)
{
    int i = blockIdx.x * 256 + threadIdx.x;
    if (i < 9*256*256) {
        int tap = i / 65536; int r = i & 65535; int ci = r >> 8; int oc = r & 255;
        g_wT[i] = cw[(oc*256 + ci)*9 + tap];
        return;
    }
    i -= 9*256*256;
    if (i < 256*48) {
        int ci = i / 48; int o = i - ci*48;
        float v = 0.f;
        if (o < 9) v = clw[o*256 + ci];
        else if (o < 45) v = bw[(o-9)*256 + ci];
        g_hw[i] = v;
        return;
    }
    i -= 256*48;
    if (i < 48) {
        float v = 0.f;
        if (i < 9) v = clb[i]; else if (i < 45) v = bb[i-9];
        g_hb[i] = v;
        return;
    }
    i -= 48;
    if (i < 36) {
        int a = i >> 2, c = i & 3;
        int si = a / 3, ri = a - si*3;
        double sc = (si == 0) ? 8.0 : (si == 1) ? 16.0 : 32.0;
        double rt = (ri == 0) ? 0.5 : (ri == 1) ? 1.0 : 2.0;
        double w = 16.0 * sc * sqrt(rt);
        double h = 16.0 * sc / sqrt(rt);
        double v = (c == 0) ? (-w*0.5) : (c == 1) ? (-h*0.5) : (c == 2) ? (w*0.5) : (h*0.5);
        g_anch[i] = (float)v;
    }
}

// ---------------- conv 3x3 + bias + relu, implicit GEMM (fp32 FFMA) ----------------
// block: 128 pixels (one image row) x 128 oc; K = 9 taps * 256 ci
__global__ __launch_bounds__(256) void conv3_kernel(const float* __restrict__ feat,
                                                    const float* __restrict__ bias)
{
    const int oc0 = blockIdx.x * 128;
    const int y   = blockIdx.y;
    const int b   = blockIdx.z;
    const int tid = threadIdx.x;
    const int tx  = tid & 15;   // oc sub-tile (8 oc)
    const int ty  = tid >> 4;   // px sub-tile (8 px)

    __shared__ __align__(16) float As[2][8][128];
    __shared__ __align__(16) float Bs[2][8][128];

    float acc[8][8];
#pragma unroll
    for (int i = 0; i < 8; i++)
#pragma unroll
        for (int j = 0; j < 8; j++) acc[i][j] = 0.f;

    float ar[4], br[4];

    auto ldg_step = [&](int s) {
        int tap = s >> 5;
        int ci0 = (s & 31) << 3;
        int ky = tap / 3, kx = tap - ky*3;
        int yy = y + ky - 1;
        bool vy = (yy >= 0) && (yy < HH);
#pragma unroll
        for (int i = 0; i < 4; i++) {
            int lin = tid + i*256;
            int cc = lin >> 7, col = lin & 127;
            int xx = col + kx - 1;
            bool v = vy && (xx >= 0) && (xx < WW);
            ar[i] = v ? __ldg(&feat[(((b*256 + ci0 + cc)*128 + yy) << 7) + xx]) : 0.f;
            br[i] = __ldg(&g_wT[((tap << 8) + ci0 + cc)*256 + oc0 + col]);
        }
    };
    auto sts_step = [&](int buf) {
#pragma unroll
        for (int i = 0; i < 4; i++) {
            int lin = tid + i*256;
            int cc = lin >> 7, col = lin & 127;
            As[buf][cc][col] = ar[i];
            Bs[buf][cc][col] = br[i];
        }
    };

    ldg_step(0);
    sts_step(0);
    __syncthreads();

    const int NS = 9 * 32;   // 288 k-steps of 8
#pragma unroll 1
    for (int s = 0; s < NS; s++) {
        int cur = s & 1;
        if (s + 1 < NS) ldg_step(s + 1);
#pragma unroll
        for (int cc = 0; cc < 8; cc++) {
            float4 a0 = *(const float4*)&As[cur][cc][ty*8];
            float4 a1 = *(const float4*)&As[cur][cc][ty*8 + 4];
            float4 b0 = *(const float4*)&Bs[cur][cc][tx*8];
            float4 b1 = *(const float4*)&Bs[cur][cc][tx*8 + 4];
            float av[8] = {a0.x,a0.y,a0.z,a0.w,a1.x,a1.y,a1.z,a1.w};
            float bv[8] = {b0.x,b0.y,b0.z,b0.w,b1.x,b1.y,b1.z,b1.w};
#pragma unroll
            for (int i = 0; i < 8; i++)
#pragma unroll
                for (int j = 0; j < 8; j++)
                    acc[i][j] += av[i] * bv[j];
        }
        if (s + 1 < NS) {
            sts_step((s + 1) & 1);
            __syncthreads();
        }
    }

    float bv[8];
#pragma unroll
    for (int j = 0; j < 8; j++) bv[j] = __ldg(&bias[oc0 + tx*8 + j]);

    float* outp = &g_t[(((size_t)(b*128 + y)*128) + (size_t)(ty*8)) * 256 + oc0 + tx*8];
#pragma unroll
    for (int i = 0; i < 8; i++) {
        float4 v0, v1;
        v0.x = fmaxf(acc[i][0] + bv[0], 0.f);
        v0.y = fmaxf(acc[i][1] + bv[1], 0.f);
        v0.z = fmaxf(acc[i][2] + bv[2], 0.f);
        v0.w = fmaxf(acc[i][3] + bv[3], 0.f);
        v1.x = fmaxf(acc[i][4] + bv[4], 0.f);
        v1.y = fmaxf(acc[i][5] + bv[5], 0.f);
        v1.z = fmaxf(acc[i][6] + bv[6], 0.f);
        v1.w = fmaxf(acc[i][7] + bv[7], 0.f);
        *(float4*)&outp[(size_t)i*256]     = v0;
        *(float4*)&outp[(size_t)i*256 + 4] = v1;
    }
}

// ---------------- heads: per 32-pixel tile, 48 outputs (9 cls + 36 bbox) ----------------
__global__ __launch_bounds__(256) void heads_kernel()
{
    __shared__ float ts[32][257];
    const int pxg0 = blockIdx.x * 32;
    const int tid  = threadIdx.x;

#pragma unroll
    for (int i = 0; i < 8; i++) {
        int f = tid + i*256;          // 2048 float4s total
        int px = f >> 6;              // 64 float4 per pixel
        int q  = f & 63;
        float4 v = *(const float4*)&g_t[((size_t)(pxg0 + px))*256 + q*4];
        ts[px][q*4+0] = v.x; ts[px][q*4+1] = v.y;
        ts[px][q*4+2] = v.z; ts[px][q*4+3] = v.w;
    }
    __syncthreads();

    const int px = tid & 31;
    const int ob = tid >> 5;          // 0..7
    const int pxg = pxg0 + px;
    const int b   = pxg >> 14;
    const int pxi = pxg & 16383;

#pragma unroll 1
    for (int c = 0; c < 6; c++) {
        int o = ob*6 + c;             // 0..47
        float acc = g_hb[o];
#pragma unroll 8
        for (int k = 0; k < 256; k++)
            acc += ts[px][k] * __ldg(&g_hw[k*48 + o]);
        if (o < 9) {
            g_scores[(size_t)b*NSC + pxi*9 + o] = acc;
        } else if (o < 45) {
            int q = o - 9;
            g_deltas[((size_t)b*NSC + pxi*9 + (q >> 2))*4 + (q & 3)] = acc;
        }
    }
}

// ---------------- exact top-600 per image: radix select + bitonic sort ----------------
__global__ __launch_bounds__(1024) void select_kernel()
{
    const int b   = blockIdx.x;
    const int tid = threadIdx.x;
    const float* sc = g_scores + (size_t)b * NSC;

    __shared__ unsigned hist[256];
    __shared__ unsigned sh_prefix, sh_want, sh_cntG, sh_cntE;
    __shared__ unsigned eqi[512];
    __shared__ unsigned long long val[1024];

    if (tid == 0) { sh_prefix = 0u; sh_want = PRE_K; sh_cntG = 0u; sh_cntE = 0u; }

    // 4-pass radix select (8 bits per pass, high to low) for the exact pivot key
    for (int p = 3; p >= 0; --p) {
        if (tid < 256) hist[tid] = 0u;
        __syncthreads();
        unsigned hm   = (p == 3) ? 0u : (0xFFFFFFFFu << ((p + 1) * 8));
        unsigned pref = sh_prefix;
        for (int n = tid; n < NSC; n += 1024) {
            unsigned k = okey(sc[n]);
            if ((k & hm) == pref) atomicAdd(&hist[(k >> (p * 8)) & 255], 1u);
        }
        __syncthreads();
        if (tid == 0) {
            unsigned want = sh_want, cum = 0; int chosen = 0;
            for (int bin = 255; bin >= 0; --bin) {
                unsigned c = hist[bin];
                if (cum + c >= want) { chosen = bin; break; }
                cum += c;
            }
            sh_want   = want - cum;                        // how many ==pivot to take
            sh_prefix = pref | ((unsigned)chosen << (p * 8));
        }
        __syncthreads();
    }
    const unsigned T = sh_prefix;
    const unsigned r = sh_want;

    // collect: all keys > T, plus the r lowest-index keys == T (jax top_k tie rule)
    for (int n = tid; n < NSC; n += 1024) {
        unsigned k = okey(sc[n]);
        if (k > T) {
            unsigned pos = atomicAdd(&sh_cntG, 1u);
            val[pos] = (((unsigned long long)k) << 32) | (unsigned long long)(0xFFFFFFFFu - (unsigned)n);
        } else if (k == T) {
            unsigned pos = atomicAdd(&sh_cntE, 1u);
            if (pos < 512) eqi[pos] = (unsigned)n;
        }
    }
    __syncthreads();
    if (tid == 0) {
        int ne = (sh_cntE < 512u) ? (int)sh_cntE : 512;
        for (int a2 = 1; a2 < ne; a2++) {                  // insertion sort asc by index
            unsigned v = eqi[a2]; int b2 = a2 - 1;
            while (b2 >= 0 && eqi[b2] > v) { eqi[b2+1] = eqi[b2]; b2--; }
            eqi[b2+1] = v;
        }
        int take = ((int)r < ne) ? (int)r : ne;
        unsigned base = sh_cntG;
        for (int q = 0; q < take; q++)
            val[base + q] = (((unsigned long long)T) << 32) | (unsigned long long)(0xFFFFFFFFu - eqi[q]);
        for (int q = take; (int)(base + q) < PRE_K && q < (int)r; q++)
            val[base + q] = 0ull;                          // pathological tie overflow guard
    }
    if (tid >= PRE_K) val[tid] = 0ull;                     // pad 600..1023 (smallest)
    __syncthreads();

    // bitonic sort 1024, descending on packed (key, ~idx) -> key desc, idx asc
    for (int k = 2; k <= 1024; k <<= 1) {
        for (int j = k >> 1; j > 0; j >>= 1) {
            int i = tid, ixj = i ^ j;
            if (ixj > i) {
                unsigned long long a = val[i], c = val[ixj];
                bool descBlock = ((i & k) == 0);
                if ((a < c) == descBlock) { val[i] = c; val[ixj] = a; }
            }
            __syncthreads();
        }
    }
    if (tid < PRE_K)
        g_topidx[b*PRE_K + tid] = 0xFFFFFFFFu - (unsigned)(val[tid] & 0xFFFFFFFFull);
}

// ---------------- decode + clip the 600 selected boxes ----------------
__global__ void decode_kernel(const int* ihp, const int* iwp)
{
    const int b = blockIdx.x, j = threadIdx.x;
    if (j >= PRE_K) return;
    const float img_h = dimval(ihp);
    const float img_w = dimval(iwp);

    unsigned n = g_topidx[b*PRE_K + j];
    int a  = n % 9;
    int px = n / 9;
    int x  = px & 127, y = px >> 7;
    float sx = x * 16.0f, sy = y * 16.0f;

    float b0 = g_anch[a*4+0], b1 = g_anch[a*4+1], b2 = g_anch[a*4+2], b3 = g_anch[a*4+3];
    // replicate reference float order: shift added first, then w/h from shifted coords
    float ax1 = b0 + sx, ay1 = b1 + sy, ax2 = b2 + sx, ay2 = b3 + sy;
    float w = ax2 - ax1, h = ay2 - ay1;
    float cx = ax1 + 0.5f*w, cy = ay1 + 0.5f*h;

    const float* d = &g_deltas[((size_t)b*NSC + n)*4];
    float dx = d[0], dy = d[1], dw = d[2], dh = d[3];
    float pcx = cx + dx*w, pcy = cy + dy*h;
    float pw = w * expf(dw), ph = h * expf(dh);
    float x1 = pcx - 0.5f*pw, y1 = pcy - 0.5f*ph;
    float x2 = pcx + 0.5f*pw, y2 = pcy + 0.5f*ph;
    x1 = fminf(fmaxf(x1, 0.f), img_w);
    y1 = fminf(fmaxf(y1, 0.f), img_h);
    x2 = fminf(fmaxf(x2, 0.f), img_w);
    y2 = fminf(fmaxf(y2, 0.f), img_h);

    float* ob = &g_boxes[(b*PRE_K + j)*4];
    ob[0] = x1; ob[1] = y1; ob[2] = x2; ob[3] = y2;
}

// ---------------- NMS suppression bitmask (600 x 19 words per image) ----------------
__global__ void nms_mask_kernel()
{
    const int b = blockIdx.z, cbk = blockIdx.x, rbk = blockIdx.y, t = threadIdx.x;
    __shared__ float4 colb[32];
    int j = cbk*32 + t;
    if (j < PRE_K) colb[t] = *(const float4*)&g_boxes[(b*PRE_K + j)*4];
    __syncthreads();

    int i = rbk*32 + t;
    if (i >= PRE_K) return;
    float4 bi = *(const float4*)&g_boxes[(b*PRE_K + i)*4];
    float ai = (bi.z - bi.x) * (bi.w - bi.y);
    unsigned bits = 0u;
#pragma unroll
    for (int jj = 0; jj < 32; jj++) {
        int jg = cbk*32 + jj;
        if (jg >= PRE_K) break;
        if (jg <= i) continue;
        float4 bj = colb[jj];
        float xx1 = fmaxf(bi.x, bj.x), yy1 = fmaxf(bi.y, bj.y);
        float xx2 = fminf(bi.z, bj.z), yy2 = fminf(bi.w, bj.w);
        float inter = fmaxf(xx2 - xx1, 0.f) * fmaxf(yy2 - yy1, 0.f);
        float aj = (bj.z - bj.x) * (bj.w - bj.y);
        float iou = inter / (ai + aj - inter);    // NaN (0/0) compares false, like jnp
        if (iou > NMS_T) bits |= (1u << jj);
    }
    g_mask[(b*PRE_K + i)*MASKW + cbk] = bits;
}

// ---------------- sequential greedy scan + emit first 100 kept, zero-fill ----------------
__global__ void final_kernel(float* __restrict__ out)
{
    const int b = blockIdx.x;
    if (threadIdx.x != 0) return;
    unsigned remv[MASKW];
#pragma unroll
    for (int w = 0; w < MASKW; w++) remv[w] = 0u;
    int nk = 0;
    for (int i = 0; i < PRE_K; i++) {
        if (!((remv[i >> 5] >> (i & 31)) & 1u)) {
            const float* bx = &g_boxes[(b*PRE_K + i)*4];
            float* o = &out[(b*POST_K + nk)*4];
            o[0] = bx[0]; o[1] = bx[1]; o[2] = bx[2]; o[3] = bx[3];
            nk++;
            if (nk >= POST_K) break;
            const unsigned* m = &g_mask[(b*PRE_K + i)*MASKW];
#pragma unroll
            for (int w = 0; w < MASKW; w++) remv[w] |= m[w];
        }
    }
    for (int k = nk; k < POST_K; k++) {
        float* o = &out[(b*POST_K + k)*4];
        o[0] = 0.f; o[1] = 0.f; o[2] = 0.f; o[3] = 0.f;
    }
}

// ---------------- launcher ----------------
extern "C" void kernel_launch(void* const* d_in, const int* in_sizes, int n_in,
                              void* d_out, int out_size)
{
    const float* feat = (const float*)d_in[0];
    const float* cw   = (const float*)d_in[1];
    const float* cb   = (const float*)d_in[2];
    const float* clw  = (const float*)d_in[3];
    const float* clb  = (const float*)d_in[4];
    const float* bw   = (const float*)d_in[5];
    const float* bb   = (const float*)d_in[6];
    const int*   ihp  = (const int*)d_in[7];
    const int*   iwp  = (const int*)d_in[8];
    float* out = (float*)d_out;

    prep_kernel<<<2353, 256>>>(cw, clw, clb, bw, bb);
    conv3_kernel<<<dim3(2, 128, 4), 256>>>(feat, cb);
    heads_kernel<<<BATCH*NPIX/32, 256>>>();
    select_kernel<<<BATCH, 1024>>>();
    decode_kernel<<<BATCH, 640>>>(ihp, iwp);
    nms_mask_kernel<<<dim3(MASKW, MASKW, BATCH), 32>>>();
    final_kernel<<<BATCH, 32>>>(out);
}

// round 6
// speedup vs baseline: 1.1832x; 1.1832x over previous
#include <cuda_runtime.h>
#include <cuda_bf16.h>
#include <cstdint>
#include <math.h>

// ---------------- problem constants ----------------
#define BATCH 4
#define CIN   256
#define HH    128
#define WW    128
#define NANCH 9
#define NPIX  (HH*WW)         // 16384
#define NSC   (NPIX*NANCH)    // 147456 per image
#define PRE_K 600
#define POST_K 100
#define NMS_T 0.7f
#define MASKW 19              // ceil(600/32)

#define FSZ ((size_t)BATCH*NPIX*CIN)     // 16777216 elems per split
#define WSZ ((size_t)256*9*256)          // 589824 elems per split

// ---------------- device scratch (static; no allocations) ----------------
__device__ __align__(16) float g_t[(size_t)BATCH*NPIX*CIN];       // conv out NHWC
__device__ __align__(16) __nv_bfloat16 g_fs[3*FSZ];               // features NHWC, bf16 x3 splits
__device__ __align__(16) __nv_bfloat16 g_wb[3*WSZ];               // weights [s][oc][tap][ci]
__device__ __align__(16) float g_hw[CIN*48];                      // [ci][48]: 9 cls + 36 bbox + 3 pad
__device__ float g_hb[48];
__device__ __align__(16) float g_anch[NANCH*4];
__device__ float g_scores[BATCH*NSC];
__device__ __align__(16) float g_deltas[(size_t)BATCH*NSC*4];
__device__ unsigned g_topidx[BATCH*PRE_K];
__device__ __align__(16) float g_boxes[BATCH*PRE_K*4];
__device__ unsigned g_mask[BATCH*PRE_K*MASKW];

// ---------------- small helpers ----------------
__device__ __forceinline__ unsigned okey(float f) {
    unsigned u = __float_as_uint(f);
    return (u & 0x80000000u) ? ~u : (u | 0x80000000u);
}
__device__ __forceinline__ float dimval(const int* p) {
    int raw = *p;
    if (raw > 0 && raw < 1000000) return (float)raw;
    return __int_as_float(raw);
}
__device__ __forceinline__ uint32_t smem_u32(const void* p) {
    uint32_t a;
    asm("{ .reg .u64 t; cvta.to.shared.u64 t, %1; cvt.u32.u64 %0, t; }" : "=r"(a) : "l"(p));
    return a;
}

// bf16x3 split of an fp32 value
__device__ __forceinline__ void split3(float v, __nv_bfloat16& h1, __nv_bfloat16& h2, __nv_bfloat16& h3) {
    h1 = __float2bfloat16_rn(v);
    float r1 = v - __bfloat162float(h1);
    h2 = __float2bfloat16_rn(r1);
    float r2 = r1 - __bfloat162float(h2);
    h3 = __float2bfloat16_rn(r2);
}

// ---------------- prep: weight split ----------------
__global__ void prep_w(const float* __restrict__ cw)
{
    int e = blockIdx.x * 256 + threadIdx.x;
    if (e >= (int)WSZ) return;
    int oc = e / 2304; int r = e - oc*2304; int tap = r >> 8; int ci = r & 255;
    float v = cw[(oc*256 + ci)*9 + tap];
    __nv_bfloat16 h1, h2, h3; split3(v, h1, h2, h3);
    g_wb[e] = h1; g_wb[WSZ + e] = h2; g_wb[2*WSZ + e] = h3;
}

// ---------------- prep: feature NCHW fp32 -> NHWC bf16 x3 ----------------
__global__ __launch_bounds__(256) void prep_f(const float* __restrict__ feat)
{
    int bid = blockIdx.x;
    int xg = bid & 3; int cg = (bid >> 2) & 7; int y = (bid >> 5) & 127; int b = bid >> 12;
    __shared__ float ts[32][33];
    int tid = threadIdx.x;
#pragma unroll
    for (int i = 0; i < 4; i++) {
        int f = tid + i*256;
        int cc = f >> 5, xx = f & 31;
        ts[cc][xx] = feat[((size_t)((b*256 + cg*32 + cc)*128 + y) << 7) + xg*32 + xx];
    }
    __syncthreads();
#pragma unroll
    for (int i = 0; i < 4; i++) {
        int f = tid + i*256;
        int xx = f >> 5, cc = f & 31;
        float v = ts[cc][xx];
        __nv_bfloat16 h1, h2, h3; split3(v, h1, h2, h3);
        size_t o = ((size_t)((b*128 + y)*128 + xg*32 + xx))*256 + cg*32 + cc;
        g_fs[o] = h1; g_fs[FSZ + o] = h2; g_fs[2*FSZ + o] = h3;
    }
}

// ---------------- prep: head weights pack + anchors ----------------
__global__ void prep_heads(const float* __restrict__ clw, const float* __restrict__ clb,
                           const float* __restrict__ bw,  const float* __restrict__ bb)
{
    int i = blockIdx.x * 256 + threadIdx.x;
    if (i < 256*48) {
        int ci = i / 48; int o = i - ci*48;
        float v = 0.f;
        if (o < 9) v = clw[o*256 + ci];
        else if (o < 45) v = bw[(o-9)*256 + ci];
        g_hw[i] = v;
        return;
    }
    i -= 256*48;
    if (i < 48) {
        float v = 0.f;
        if (i < 9) v = clb[i]; else if (i < 45) v = bb[i-9];
        g_hb[i] = v;
        return;
    }
    i -= 48;
    if (i < 36) {
        int a = i >> 2, c = i & 3;
        int si = a / 3, ri = a - si*3;
        double sc = (si == 0) ? 8.0 : (si == 1) ? 16.0 : 32.0;
        double rt = (ri == 0) ? 0.5 : (ri == 1) ? 1.0 : 2.0;
        double w = 16.0 * sc * sqrt(rt);
        double h = 16.0 * sc / sqrt(rt);
        double v = (c == 0) ? (-w*0.5) : (c == 1) ? (-h*0.5) : (c == 2) ? (w*0.5) : (h*0.5);
        g_anch[i] = (float)v;
    }
}

// ---------------- conv 3x3 + bias + relu via mma.sync bf16x3 (sm_80-class HMMA) ----------------
// CTA: M=128 px (one y-row) x N=128 oc; K-chunk=32 ci of one tap; 72 chunks.
// SMEM per stage: (A + B) = 3 splits * 128 rows * 80B = 30720B each -> 61440B; two stages.
// Row stride 80B (5*16B, gcd(5,8)=1) -> conflict-free ldmatrix without swizzle.
#define ROWB   80
#define SPL_SZ (128*ROWB)            // 10240 B per split tile
#define AB_SZ  (3*SPL_SZ)            // 30720
#define STG_SZ (2*AB_SZ)             // 61440
#define SM_TOTAL (2*STG_SZ)          // 122880

#define LDMX4(r0,r1,r2,r3,addr) \
    asm volatile("ldmatrix.sync.aligned.m8n8.x4.shared.b16 {%0,%1,%2,%3}, [%4];" \
        : "=r"(r0), "=r"(r1), "=r"(r2), "=r"(r3) : "r"(addr))

#define MMA16816(d,a,b) \
    asm volatile("mma.sync.aligned.m16n8k16.row.col.f32.bf16.bf16.f32 " \
        "{%0,%1,%2,%3}, {%4,%5,%6,%7}, {%8,%9}, {%0,%1,%2,%3};" \
        : "+f"((d)[0]), "+f"((d)[1]), "+f"((d)[2]), "+f"((d)[3]) \
        : "r"((a)[0]), "r"((a)[1]), "r"((a)[2]), "r"((a)[3]), "r"((b)[0]), "r"((b)[1]))

extern __shared__ char cv_smem[];

__global__ __launch_bounds__(256) void conv_tc(const float* __restrict__ bias)
{
    char* smem = cv_smem;
    const uint32_t sbase = smem_u32(smem);
    const int tid  = threadIdx.x;
    const int wid  = tid >> 5;
    const int lane = tid & 31;
    const int wm   = wid & 3;        // M group (32 px)
    const int wn   = wid >> 2;       // N group (64 oc)
    const int oc0  = blockIdx.x * 128;
    const int y    = blockIdx.y;
    const int b    = blockIdx.z;

    float acc[2][8][4];
#pragma unroll
    for (int mt = 0; mt < 2; mt++)
#pragma unroll
        for (int nt = 0; nt < 8; nt++)
#pragma unroll
            for (int q = 0; q < 4; q++) acc[mt][nt][q] = 0.f;

    uint4 pre[12];

    auto ldg_chunk = [&](int kc) {
        int tap = kc >> 3, ci0 = (kc & 7) << 5;
        int ky = tap / 3, kx = tap - ky*3;
        int yy = y + ky - 1;
        bool vy = ((unsigned)yy < 128u);
#pragma unroll
        for (int i = 0; i < 12; i++) {
            int v = tid + i*256;              // 0..3071
            int ab = v >= 1536;
            int r  = ab ? v - 1536 : v;
            int s  = r >> 9;
            int r2 = r & 511;
            int row = r2 >> 2;
            int c   = r2 & 3;
            if (!ab) {
                int xx = row + kx - 1;
                uint4 val = make_uint4(0u,0u,0u,0u);
                if (vy && ((unsigned)xx < 128u))
                    val = *(const uint4*)(g_fs + (size_t)s*FSZ + ((size_t)((b*128 + yy)*128 + xx))*256 + ci0 + c*8);
                pre[i] = val;
            } else {
                pre[i] = *(const uint4*)(g_wb + (size_t)s*WSZ + ((size_t)((oc0 + row)*9 + tap))*256 + ci0 + c*8);
            }
        }
    };
    auto sts_chunk = [&](int st) {
#pragma unroll
        for (int i = 0; i < 12; i++) {
            int v = tid + i*256;
            int ab = v >= 1536;
            int r  = ab ? v - 1536 : v;
            int s  = r >> 9;
            int r2 = r & 511;
            int row = r2 >> 2;
            int c   = r2 & 3;
            *(uint4*)(smem + st*STG_SZ + ab*AB_SZ + s*SPL_SZ + row*ROWB + c*16) = pre[i];
        }
    };

    auto compute = [&](int st) {
        const uint32_t abase = sbase + st*STG_SZ;
        const uint32_t bbase = abase + AB_SZ;
#pragma unroll
        for (int h = 0; h < 2; h++) {
            uint32_t colo = h*32 + ((lane >> 4) << 4);
            // A fragments, all 3 splits, 2 M-tiles each
            uint32_t afr[3][2][4];
#pragma unroll
            for (int s = 0; s < 3; s++) {
#pragma unroll
                for (int mt = 0; mt < 2; mt++) {
                    uint32_t addr = abase + s*SPL_SZ + (wm*32 + mt*16 + (lane & 15))*ROWB + colo;
                    LDMX4(afr[s][mt][0], afr[s][mt][1], afr[s][mt][2], afr[s][mt][3], addr);
                }
            }
#pragma unroll
            for (int sb = 0; sb < 3; sb++) {
                uint32_t bfr[8][2];
#pragma unroll
                for (int p = 0; p < 4; p++) {
                    uint32_t r0, r1, r2, r3;
                    uint32_t addr = bbase + sb*SPL_SZ + (wn*64 + p*16 + (lane & 15))*ROWB + colo;
                    LDMX4(r0, r1, r2, r3, addr);
                    bfr[2*p][0] = r0; bfr[2*p][1] = r2;
                    bfr[2*p+1][0] = r1; bfr[2*p+1][1] = r3;
                }
                int nA = (sb == 0) ? 3 : (sb == 1) ? 2 : 1;
#pragma unroll
                for (int sa = 0; sa < 3; sa++) {
                    if (sa >= nA) break;
#pragma unroll
                    for (int mt = 0; mt < 2; mt++)
#pragma unroll
                        for (int nt = 0; nt < 8; nt++)
                            MMA16816(acc[mt][nt], afr[sa][mt], bfr[nt]);
                }
            }
        }
    };

    ldg_chunk(0);
    sts_chunk(0);
    __syncthreads();

    const int NCH = 72;
#pragma unroll 1
    for (int c = 0; c < NCH; c++) {
        int cur = c & 1;
        if (c + 1 < NCH) ldg_chunk(c + 1);
        compute(cur);
        __syncthreads();
        if (c + 1 < NCH) {
            sts_chunk(cur ^ 1);
            __syncthreads();
        }
    }

    // epilogue: bias + relu, direct float2 stores to NHWC g_t
    const int gid = lane >> 2, tg = lane & 3;
    float* base = g_t + ((size_t)((b*128 + y)*128))*256 + oc0;
#pragma unroll
    for (int mt = 0; mt < 2; mt++) {
#pragma unroll
        for (int nt = 0; nt < 8; nt++) {
            int col = wn*64 + nt*8 + tg*2;
            float b0 = __ldg(&bias[oc0 + col]);
            float b1 = __ldg(&bias[oc0 + col + 1]);
            int px0 = wm*32 + mt*16 + gid;
            float2 v0, v1;
            v0.x = fmaxf(acc[mt][nt][0] + b0, 0.f);
            v0.y = fmaxf(acc[mt][nt][1] + b1, 0.f);
            v1.x = fmaxf(acc[mt][nt][2] + b0, 0.f);
            v1.y = fmaxf(acc[mt][nt][3] + b1, 0.f);
            *(float2*)(base + (size_t)px0*256 + col)       = v0;
            *(float2*)(base + (size_t)(px0 + 8)*256 + col) = v1;
        }
    }
}

// ---------------- heads: per 32-pixel tile, 48 outputs ----------------
__global__ __launch_bounds__(256) void heads_kernel()
{
    __shared__ float ts[32][257];
    const int pxg0 = blockIdx.x * 32;
    const int tid  = threadIdx.x;

#pragma unroll
    for (int i = 0; i < 8; i++) {
        int f = tid + i*256;
        int px = f >> 6;
        int q  = f & 63;
        float4 v = *(const float4*)&g_t[((size_t)(pxg0 + px))*256 + q*4];
        ts[px][q*4+0] = v.x; ts[px][q*4+1] = v.y;
        ts[px][q*4+2] = v.z; ts[px][q*4+3] = v.w;
    }
    __syncthreads();

    const int px = tid & 31;
    const int ob = tid >> 5;
    const int pxg = pxg0 + px;
    const int b   = pxg >> 14;
    const int pxi = pxg & 16383;

#pragma unroll 1
    for (int c = 0; c < 6; c++) {
        int o = ob*6 + c;
        float acc = g_hb[o];
#pragma unroll 8
        for (int k = 0; k < 256; k++)
            acc += ts[px][k] * __ldg(&g_hw[k*48 + o]);
        if (o < 9) {
            g_scores[(size_t)b*NSC + pxi*9 + o] = acc;
        } else if (o < 45) {
            int q = o - 9;
            g_deltas[((size_t)b*NSC + pxi*9 + (q >> 2))*4 + (q & 3)] = acc;
        }
    }
}

// ---------------- exact top-600 per image: radix select + bitonic sort ----------------
__global__ __launch_bounds__(1024) void select_kernel()
{
    const int b   = blockIdx.x;
    const int tid = threadIdx.x;
    const float* sc = g_scores + (size_t)b * NSC;

    __shared__ unsigned hist[256];
    __shared__ unsigned sh_prefix, sh_want, sh_cntG, sh_cntE;
    __shared__ unsigned eqi[512];
    __shared__ unsigned long long val[1024];

    if (tid == 0) { sh_prefix = 0u; sh_want = PRE_K; sh_cntG = 0u; sh_cntE = 0u; }

    for (int p = 3; p >= 0; --p) {
        if (tid < 256) hist[tid] = 0u;
        __syncthreads();
        unsigned hm   = (p == 3) ? 0u : (0xFFFFFFFFu << ((p + 1) * 8));
        unsigned pref = sh_prefix;
        for (int n = tid; n < NSC; n += 1024) {
            unsigned k = okey(sc[n]);
            if ((k & hm) == pref) atomicAdd(&hist[(k >> (p * 8)) & 255], 1u);
        }
        __syncthreads();
        if (tid == 0) {
            unsigned want = sh_want, cum = 0; int chosen = 0;
            for (int bin = 255; bin >= 0; --bin) {
                unsigned c = hist[bin];
                if (cum + c >= want) { chosen = bin; break; }
                cum += c;
            }
            sh_want   = want - cum;
            sh_prefix = pref | ((unsigned)chosen << (p * 8));
        }
        __syncthreads();
    }
    const unsigned T = sh_prefix;
    const unsigned r = sh_want;

    for (int n = tid; n < NSC; n += 1024) {
        unsigned k = okey(sc[n]);
        if (k > T) {
            unsigned pos = atomicAdd(&sh_cntG, 1u);
            val[pos] = (((unsigned long long)k) << 32) | (unsigned long long)(0xFFFFFFFFu - (unsigned)n);
        } else if (k == T) {
            unsigned pos = atomicAdd(&sh_cntE, 1u);
            if (pos < 512) eqi[pos] = (unsigned)n;
        }
    }
    __syncthreads();
    if (tid == 0) {
        int ne = (sh_cntE < 512u) ? (int)sh_cntE : 512;
        for (int a2 = 1; a2 < ne; a2++) {
            unsigned v = eqi[a2]; int b2 = a2 - 1;
            while (b2 >= 0 && eqi[b2] > v) { eqi[b2+1] = eqi[b2]; b2--; }
            eqi[b2+1] = v;
        }
        int take = ((int)r < ne) ? (int)r : ne;
        unsigned base = sh_cntG;
        for (int q = 0; q < take; q++)
            val[base + q] = (((unsigned long long)T) << 32) | (unsigned long long)(0xFFFFFFFFu - eqi[q]);
        for (int q = take; (int)(base + q) < PRE_K && q < (int)r; q++)
            val[base + q] = 0ull;
    }
    if (tid >= PRE_K) val[tid] = 0ull;
    __syncthreads();

    for (int k = 2; k <= 1024; k <<= 1) {
        for (int j = k >> 1; j > 0; j >>= 1) {
            int i = tid, ixj = i ^ j;
            if (ixj > i) {
                unsigned long long a = val[i], c = val[ixj];
                bool descBlock = ((i & k) == 0);
                if ((a < c) == descBlock) { val[i] = c; val[ixj] = a; }
            }
            __syncthreads();
        }
    }
    if (tid < PRE_K)
        g_topidx[b*PRE_K + tid] = 0xFFFFFFFFu - (unsigned)(val[tid] & 0xFFFFFFFFull);
}

// ---------------- decode + clip ----------------
__global__ void decode_kernel(const int* ihp, const int* iwp)
{
    const int b = blockIdx.x, j = threadIdx.x;
    if (j >= PRE_K) return;
    const float img_h = dimval(ihp);
    const float img_w = dimval(iwp);

    unsigned n = g_topidx[b*PRE_K + j];
    int a  = n % 9;
    int px = n / 9;
    int x  = px & 127, y = px >> 7;
    float sx = x * 16.0f, sy = y * 16.0f;

    float b0 = g_anch[a*4+0], b1 = g_anch[a*4+1], b2 = g_anch[a*4+2], b3 = g_anch[a*4+3];
    float ax1 = b0 + sx, ay1 = b1 + sy, ax2 = b2 + sx, ay2 = b3 + sy;
    float w = ax2 - ax1, h = ay2 - ay1;
    float cx = ax1 + 0.5f*w, cy = ay1 + 0.5f*h;

    const float* d = &g_deltas[((size_t)b*NSC + n)*4];
    float dx = d[0], dy = d[1], dw = d[2], dh = d[3];
    float pcx = cx + dx*w, pcy = cy + dy*h;
    float pw = w * expf(dw), ph = h * expf(dh);
    float x1 = pcx - 0.5f*pw, y1 = pcy - 0.5f*ph;
    float x2 = pcx + 0.5f*pw, y2 = pcy + 0.5f*ph;
    x1 = fminf(fmaxf(x1, 0.f), img_w);
    y1 = fminf(fmaxf(y1, 0.f), img_h);
    x2 = fminf(fmaxf(x2, 0.f), img_w);
    y2 = fminf(fmaxf(y2, 0.f), img_h);

    float* ob = &g_boxes[(b*PRE_K + j)*4];
    ob[0] = x1; ob[1] = y1; ob[2] = x2; ob[3] = y2;
}

// ---------------- NMS suppression bitmask ----------------
__global__ void nms_mask_kernel()
{
    const int b = blockIdx.z, cbk = blockIdx.x, rbk = blockIdx.y, t = threadIdx.x;
    __shared__ float4 colb[32];
    int j = cbk*32 + t;
    if (j < PRE_K) colb[t] = *(const float4*)&g_boxes[(b*PRE_K + j)*4];
    __syncthreads();

    int i = rbk*32 + t;
    if (i >= PRE_K) return;
    float4 bi = *(const float4*)&g_boxes[(b*PRE_K + i)*4];
    float ai = (bi.z - bi.x) * (bi.w - bi.y);
    unsigned bits = 0u;
#pragma unroll
    for (int jj = 0; jj < 32; jj++) {
        int jg = cbk*32 + jj;
        if (jg >= PRE_K) break;
        if (jg <= i) continue;
        float4 bj = colb[jj];
        float xx1 = fmaxf(bi.x, bj.x), yy1 = fmaxf(bi.y, bj.y);
        float xx2 = fminf(bi.z, bj.z), yy2 = fminf(bi.w, bj.w);
        float inter = fmaxf(xx2 - xx1, 0.f) * fmaxf(yy2 - yy1, 0.f);
        float aj = (bj.z - bj.x) * (bj.w - bj.y);
        float iou = inter / (ai + aj - inter);
        if (iou > NMS_T) bits |= (1u << jj);
    }
    g_mask[(b*PRE_K + i)*MASKW + cbk] = bits;
}

// ---------------- sequential greedy scan + emit ----------------
__global__ void final_kernel(float* __restrict__ out)
{
    const int b = blockIdx.x;
    if (threadIdx.x != 0) return;
    unsigned remv[MASKW];
#pragma unroll
    for (int w = 0; w < MASKW; w++) remv[w] = 0u;
    int nk = 0;
    for (int i = 0; i < PRE_K; i++) {
        if (!((remv[i >> 5] >> (i & 31)) & 1u)) {
            const float* bx = &g_boxes[(b*PRE_K + i)*4];
            float* o = &out[(b*POST_K + nk)*4];
            o[0] = bx[0]; o[1] = bx[1]; o[2] = bx[2]; o[3] = bx[3];
            nk++;
            if (nk >= POST_K) break;
            const unsigned* m = &g_mask[(b*PRE_K + i)*MASKW];
#pragma unroll
            for (int w = 0; w < MASKW; w++) remv[w] |= m[w];
        }
    }
    for (int k = nk; k < POST_K; k++) {
        float* o = &out[(b*POST_K + k)*4];
        o[0] = 0.f; o[1] = 0.f; o[2] = 0.f; o[3] = 0.f;
    }
}

// ---------------- launcher ----------------
extern "C" void kernel_launch(void* const* d_in, const int* in_sizes, int n_in,
                              void* d_out, int out_size)
{
    const float* feat = (const float*)d_in[0];
    const float* cw   = (const float*)d_in[1];
    const float* cb   = (const float*)d_in[2];
    const float* clw  = (const float*)d_in[3];
    const float* clb  = (const float*)d_in[4];
    const float* bw   = (const float*)d_in[5];
    const float* bb   = (const float*)d_in[6];
    const int*   ihp  = (const int*)d_in[7];
    const int*   iwp  = (const int*)d_in[8];
    float* out = (float*)d_out;

    static int smem_set = 0;
    if (!smem_set) {
        cudaFuncSetAttribute(conv_tc, cudaFuncAttributeMaxDynamicSharedMemorySize, SM_TOTAL);
        smem_set = 1;
    }

    prep_w<<<2304, 256>>>(cw);
    prep_f<<<16384, 256>>>(feat);
    prep_heads<<<49, 256>>>(clw, clb, bw, bb);
    conv_tc<<<dim3(2, 128, 4), 256, SM_TOTAL>>>(cb);
    heads_kernel<<<BATCH*NPIX/32, 256>>>();
    select_kernel<<<BATCH, 1024>>>();
    decode_kernel<<<BATCH, 640>>>(ihp, iwp);
    nms_mask_kernel<<<dim3(MASKW, MASKW, BATCH), 32>>>();
    final_kernel<<<BATCH, 32>>>(out);
}

// round 7
// speedup vs baseline: 1.2017x; 1.0156x over previous
#include <cuda_runtime.h>
#include <cuda_bf16.h>
#include <cstdint>
#include <math.h>

// ---------------- problem constants ----------------
#define BATCH 4
#define CIN   256
#define HH    128
#define WW    128
#define NANCH 9
#define NPIX  (HH*WW)         // 16384
#define NSC   (NPIX*NANCH)    // 147456 per image
#define PRE_K 600
#define POST_K 100
#define NMS_T 0.7f
#define MASKW 19              // ceil(600/32)

#define FSZ ((size_t)BATCH*NPIX*CIN)     // 16777216 elems per split
#define WSZ ((size_t)256*9*256)          // 589824 elems per split

// ---------------- device scratch (static; no allocations) ----------------
__device__ __align__(16) float g_t[(size_t)BATCH*NPIX*CIN];       // conv out NHWC
__device__ __align__(16) __nv_bfloat16 g_fs[3*FSZ];               // features NHWC, bf16 x3 splits
__device__ __align__(16) __nv_bfloat16 g_wb[3*WSZ];               // weights [s][oc][tap][ci]
__device__ __align__(16) float g_hw[CIN*48];                      // [ci][48]: 9 cls + 36 bbox + 3 pad
__device__ float g_hb[48];
__device__ __align__(16) float g_anch[NANCH*4];
__device__ float g_scores[BATCH*NSC];
__device__ __align__(16) float g_deltas[(size_t)BATCH*NSC*4];
__device__ unsigned g_topidx[BATCH*PRE_K];
__device__ __align__(16) float g_boxes[BATCH*PRE_K*4];
__device__ unsigned g_mask[BATCH*PRE_K*MASKW];

// ---------------- small helpers ----------------
__device__ __forceinline__ unsigned okey(float f) {
    unsigned u = __float_as_uint(f);
    return (u & 0x80000000u) ? ~u : (u | 0x80000000u);
}
__device__ __forceinline__ float dimval(const int* p) {
    int raw = *p;
    if (raw > 0 && raw < 1000000) return (float)raw;
    return __int_as_float(raw);
}
__device__ __forceinline__ uint32_t smem_u32(const void* p) {
    uint32_t a;
    asm("{ .reg .u64 t; cvta.to.shared.u64 t, %1; cvt.u32.u64 %0, t; }" : "=r"(a) : "l"(p));
    return a;
}

// bf16x3 split of an fp32 value
__device__ __forceinline__ void split3(float v, __nv_bfloat16& h1, __nv_bfloat16& h2, __nv_bfloat16& h3) {
    h1 = __float2bfloat16_rn(v);
    float r1 = v - __bfloat162float(h1);
    h2 = __float2bfloat16_rn(r1);
    float r2 = r1 - __bfloat162float(h2);
    h3 = __float2bfloat16_rn(r2);
}

// ---------------- prep: weight split ----------------
__global__ void prep_w(const float* __restrict__ cw)
{
    int e = blockIdx.x * 256 + threadIdx.x;
    if (e >= (int)WSZ) return;
    int oc = e / 2304; int r = e - oc*2304; int tap = r >> 8; int ci = r & 255;
    float v = cw[(oc*256 + ci)*9 + tap];
    __nv_bfloat16 h1, h2, h3; split3(v, h1, h2, h3);
    g_wb[e] = h1; g_wb[WSZ + e] = h2; g_wb[2*WSZ + e] = h3;
}

// ---------------- prep: feature NCHW fp32 -> NHWC bf16 x3 ----------------
__global__ __launch_bounds__(256) void prep_f(const float* __restrict__ feat)
{
    int bid = blockIdx.x;
    int xg = bid & 3; int cg = (bid >> 2) & 7; int y = (bid >> 5) & 127; int b = bid >> 12;
    __shared__ float ts[32][33];
    int tid = threadIdx.x;
#pragma unroll
    for (int i = 0; i < 4; i++) {
        int f = tid + i*256;
        int cc = f >> 5, xx = f & 31;
        ts[cc][xx] = feat[((size_t)((b*256 + cg*32 + cc)*128 + y) << 7) + xg*32 + xx];
    }
    __syncthreads();
#pragma unroll
    for (int i = 0; i < 4; i++) {
        int f = tid + i*256;
        int xx = f >> 5, cc = f & 31;
        float v = ts[cc][xx];
        __nv_bfloat16 h1, h2, h3; split3(v, h1, h2, h3);
        size_t o = ((size_t)((b*128 + y)*128 + xg*32 + xx))*256 + cg*32 + cc;
        g_fs[o] = h1; g_fs[FSZ + o] = h2; g_fs[2*FSZ + o] = h3;
    }
}

// ---------------- prep: head weights pack + anchors ----------------
__global__ void prep_heads(const float* __restrict__ clw, const float* __restrict__ clb,
                           const float* __restrict__ bw,  const float* __restrict__ bb)
{
    int i = blockIdx.x * 256 + threadIdx.x;
    if (i < 256*48) {
        int ci = i / 48; int o = i - ci*48;
        float v = 0.f;
        if (o < 9) v = clw[o*256 + ci];
        else if (o < 45) v = bw[(o-9)*256 + ci];
        g_hw[i] = v;
        return;
    }
    i -= 256*48;
    if (i < 48) {
        float v = 0.f;
        if (i < 9) v = clb[i]; else if (i < 45) v = bb[i-9];
        g_hb[i] = v;
        return;
    }
    i -= 48;
    if (i < 36) {
        int a = i >> 2, c = i & 3;
        int si = a / 3, ri = a - si*3;
        double sc = (si == 0) ? 8.0 : (si == 1) ? 16.0 : 32.0;
        double rt = (ri == 0) ? 0.5 : (ri == 1) ? 1.0 : 2.0;
        double w = 16.0 * sc * sqrt(rt);
        double h = 16.0 * sc / sqrt(rt);
        double v = (c == 0) ? (-w*0.5) : (c == 1) ? (-h*0.5) : (c == 2) ? (w*0.5) : (h*0.5);
        g_anch[i] = (float)v;
    }
}

// ---------------- conv 3x3 + bias + relu via mma.sync bf16x3 + cp.async ----------------
// CTA: M=128 px (one y-row) x N=128 oc; K-chunk=32 ci of one tap; 72 chunks.
// 3-stage cp.async pipeline. Stage: (A + B) = 3 splits * 128 rows * 80B stride (64B payload).
// Row stride 80B (5*16B, gcd(5,8)=1) -> conflict-free ldmatrix without swizzle.
#define ROWB   80
#define SPL_SZ (128*ROWB)            // 10240 B per split tile
#define AB_SZ  (3*SPL_SZ)            // 30720
#define STG_SZ (2*AB_SZ)             // 61440
#define NSTG   3
#define SM_TOTAL (NSTG*STG_SZ)       // 184320

#define LDMX4(r0,r1,r2,r3,addr) \
    asm volatile("ldmatrix.sync.aligned.m8n8.x4.shared.b16 {%0,%1,%2,%3}, [%4];" \
        : "=r"(r0), "=r"(r1), "=r"(r2), "=r"(r3) : "r"(addr))

#define MMA16816(d,a,b) \
    asm volatile("mma.sync.aligned.m16n8k16.row.col.f32.bf16.bf16.f32 " \
        "{%0,%1,%2,%3}, {%4,%5,%6,%7}, {%8,%9}, {%0,%1,%2,%3};" \
        : "+f"((d)[0]), "+f"((d)[1]), "+f"((d)[2]), "+f"((d)[3]) \
        : "r"((a)[0]), "r"((a)[1]), "r"((a)[2]), "r"((a)[3]), "r"((b)[0]), "r"((b)[1]))

#define CP_ASYNC16(daddr, gptr, sz) \
    asm volatile("cp.async.cg.shared.global [%0], [%1], 16, %2;" \
        :: "r"(daddr), "l"(gptr), "r"(sz))
#define CP_COMMIT() asm volatile("cp.async.commit_group;" ::: "memory")
#define CP_WAIT2()  asm volatile("cp.async.wait_group 2;" ::: "memory")
#define CP_WAIT0()  asm volatile("cp.async.wait_group 0;" ::: "memory")

extern __shared__ char cv_smem[];

__global__ __launch_bounds__(256) void conv_tc(const float* __restrict__ bias)
{
    char* smem = cv_smem;
    const uint32_t sbase = smem_u32(smem);
    const int tid  = threadIdx.x;
    const int wid  = tid >> 5;
    const int lane = tid & 31;
    const int wm   = wid & 3;        // M group (32 px)
    const int wn   = wid >> 2;       // N group (64 oc)
    const int oc0  = blockIdx.x * 128;
    const int y    = blockIdx.y;
    const int b    = blockIdx.z;

    float acc[2][8][4];
#pragma unroll
    for (int mt = 0; mt < 2; mt++)
#pragma unroll
        for (int nt = 0; nt < 8; nt++)
#pragma unroll
            for (int q = 0; q < 4; q++) acc[mt][nt][q] = 0.f;

    // precompute per-thread copy roles (12 x 16B per thread per stage)
    auto issue_stage = [&](int kc) {
        const int st = kc % NSTG;
        const int tap = kc >> 3, ci0 = (kc & 7) << 5;
        const int ky = tap / 3, kx = tap - ky*3;
        const int yy = y + ky - 1;
        const bool vy = ((unsigned)yy < 128u);
#pragma unroll
        for (int i = 0; i < 12; i++) {
            int v = tid + i*256;              // 0..3071
            int ab = v >= 1536;
            int r  = ab ? v - 1536 : v;
            int s  = r >> 9;
            int r2 = r & 511;
            int row = r2 >> 2;
            int c   = r2 & 3;                 // 4 x 16B = 64B payload per row
            uint32_t daddr = sbase + st*STG_SZ + ab*AB_SZ + s*SPL_SZ + row*ROWB + c*16;
            if (!ab) {
                int xx = row + kx - 1;
                bool ok = vy && ((unsigned)xx < 128u);
                const __nv_bfloat16* gp = ok
                    ? g_fs + (size_t)s*FSZ + ((size_t)((b*128 + yy)*128 + xx))*256 + ci0 + c*8
                    : g_fs;                   // dummy valid address; sz=0 -> zero-fill
                CP_ASYNC16(daddr, gp, ok ? 16 : 0);
            } else {
                const __nv_bfloat16* gp = g_wb + (size_t)s*WSZ + ((size_t)((oc0 + row)*9 + tap))*256 + ci0 + c*8;
                CP_ASYNC16(daddr, gp, 16);
            }
        }
        CP_COMMIT();
    };

    auto compute = [&](int st) {
        const uint32_t abase = sbase + st*STG_SZ;
        const uint32_t bbase = abase + AB_SZ;
#pragma unroll
        for (int h = 0; h < 2; h++) {
            uint32_t colo = h*32 + ((lane >> 4) << 4);
            uint32_t afr[3][2][4];
#pragma unroll
            for (int s = 0; s < 3; s++) {
#pragma unroll
                for (int mt = 0; mt < 2; mt++) {
                    uint32_t addr = abase + s*SPL_SZ + (wm*32 + mt*16 + (lane & 15))*ROWB + colo;
                    LDMX4(afr[s][mt][0], afr[s][mt][1], afr[s][mt][2], afr[s][mt][3], addr);
                }
            }
#pragma unroll
            for (int sb = 0; sb < 3; sb++) {
                uint32_t bfr[8][2];
#pragma unroll
                for (int p = 0; p < 4; p++) {
                    uint32_t r0, r1, r2, r3;
                    uint32_t addr = bbase + sb*SPL_SZ + (wn*64 + p*16 + (lane & 15))*ROWB + colo;
                    LDMX4(r0, r1, r2, r3, addr);
                    bfr[2*p][0] = r0;   bfr[2*p][1] = r2;
                    bfr[2*p+1][0] = r1; bfr[2*p+1][1] = r3;
                }
                int nA = (sb == 0) ? 3 : (sb == 1) ? 2 : 1;
#pragma unroll
                for (int sa = 0; sa < 3; sa++) {
                    if (sa >= nA) break;
#pragma unroll
                    for (int mt = 0; mt < 2; mt++)
#pragma unroll
                        for (int nt = 0; nt < 8; nt++)
                            MMA16816(acc[mt][nt], afr[sa][mt], bfr[nt]);
                }
            }
        }
    };

    const int NCH = 72;
    issue_stage(0);
    issue_stage(1);
#pragma unroll 1
    for (int c = 0; c < NCH; c++) {
        if (c + 2 < NCH) { issue_stage(c + 2); CP_WAIT2(); }
        else             { CP_WAIT0(); }
        __syncthreads();
        compute(c % NSTG);
        __syncthreads();
    }

    // epilogue: bias + relu, direct float2 stores to NHWC g_t
    const int gid = lane >> 2, tg = lane & 3;
    float* base = g_t + ((size_t)((b*128 + y)*128))*256 + oc0;
#pragma unroll
    for (int mt = 0; mt < 2; mt++) {
#pragma unroll
        for (int nt = 0; nt < 8; nt++) {
            int col = wn*64 + nt*8 + tg*2;
            float b0 = __ldg(&bias[oc0 + col]);
            float b1 = __ldg(&bias[oc0 + col + 1]);
            int px0 = wm*32 + mt*16 + gid;
            float2 v0, v1;
            v0.x = fmaxf(acc[mt][nt][0] + b0, 0.f);
            v0.y = fmaxf(acc[mt][nt][1] + b1, 0.f);
            v1.x = fmaxf(acc[mt][nt][2] + b0, 0.f);
            v1.y = fmaxf(acc[mt][nt][3] + b1, 0.f);
            *(float2*)(base + (size_t)px0*256 + col)       = v0;
            *(float2*)(base + (size_t)(px0 + 8)*256 + col) = v1;
        }
    }
}

// ---------------- heads: per 32-pixel tile, 48 outputs ----------------
__global__ __launch_bounds__(256) void heads_kernel()
{
    __shared__ float ts[32][257];
    const int pxg0 = blockIdx.x * 32;
    const int tid  = threadIdx.x;

#pragma unroll
    for (int i = 0; i < 8; i++) {
        int f = tid + i*256;
        int px = f >> 6;
        int q  = f & 63;
        float4 v = *(const float4*)&g_t[((size_t)(pxg0 + px))*256 + q*4];
        ts[px][q*4+0] = v.x; ts[px][q*4+1] = v.y;
        ts[px][q*4+2] = v.z; ts[px][q*4+3] = v.w;
    }
    __syncthreads();

    const int px = tid & 31;
    const int ob = tid >> 5;
    const int pxg = pxg0 + px;
    const int b   = pxg >> 14;
    const int pxi = pxg & 16383;

#pragma unroll 1
    for (int c = 0; c < 6; c++) {
        int o = ob*6 + c;
        float acc = g_hb[o];
#pragma unroll 8
        for (int k = 0; k < 256; k++)
            acc += ts[px][k] * __ldg(&g_hw[k*48 + o]);
        if (o < 9) {
            g_scores[(size_t)b*NSC + pxi*9 + o] = acc;
        } else if (o < 45) {
            int q = o - 9;
            g_deltas[((size_t)b*NSC + pxi*9 + (q >> 2))*4 + (q & 3)] = acc;
        }
    }
}

// ---------------- exact top-600 per image: radix select + bitonic sort ----------------
__global__ __launch_bounds__(1024) void select_kernel()
{
    const int b   = blockIdx.x;
    const int tid = threadIdx.x;
    const float* sc = g_scores + (size_t)b * NSC;

    __shared__ unsigned hist[256];
    __shared__ unsigned sh_prefix, sh_want, sh_cntG, sh_cntE;
    __shared__ unsigned eqi[512];
    __shared__ unsigned long long val[1024];

    if (tid == 0) { sh_prefix = 0u; sh_want = PRE_K; sh_cntG = 0u; sh_cntE = 0u; }

    for (int p = 3; p >= 0; --p) {
        if (tid < 256) hist[tid] = 0u;
        __syncthreads();
        unsigned hm   = (p == 3) ? 0u : (0xFFFFFFFFu << ((p + 1) * 8));
        unsigned pref = sh_prefix;
        for (int n = tid; n < NSC; n += 1024) {
            unsigned k = okey(sc[n]);
            if ((k & hm) == pref) atomicAdd(&hist[(k >> (p * 8)) & 255], 1u);
        }
        __syncthreads();
        if (tid == 0) {
            unsigned want = sh_want, cum = 0; int chosen = 0;
            for (int bin = 255; bin >= 0; --bin) {
                unsigned c = hist[bin];
                if (cum + c >= want) { chosen = bin; break; }
                cum += c;
            }
            sh_want   = want - cum;
            sh_prefix = pref | ((unsigned)chosen << (p * 8));
        }
        __syncthreads();
    }
    const unsigned T = sh_prefix;
    const unsigned r = sh_want;

    for (int n = tid; n < NSC; n += 1024) {
        unsigned k = okey(sc[n]);
        if (k > T) {
            unsigned pos = atomicAdd(&sh_cntG, 1u);
            val[pos] = (((unsigned long long)k) << 32) | (unsigned long long)(0xFFFFFFFFu - (unsigned)n);
        } else if (k == T) {
            unsigned pos = atomicAdd(&sh_cntE, 1u);
            if (pos < 512) eqi[pos] = (unsigned)n;
        }
    }
    __syncthreads();
    if (tid == 0) {
        int ne = (sh_cntE < 512u) ? (int)sh_cntE : 512;
        for (int a2 = 1; a2 < ne; a2++) {
            unsigned v = eqi[a2]; int b2 = a2 - 1;
            while (b2 >= 0 && eqi[b2] > v) { eqi[b2+1] = eqi[b2]; b2--; }
            eqi[b2+1] = v;
        }
        int take = ((int)r < ne) ? (int)r : ne;
        unsigned base = sh_cntG;
        for (int q = 0; q < take; q++)
            val[base + q] = (((unsigned long long)T) << 32) | (unsigned long long)(0xFFFFFFFFu - eqi[q]);
        for (int q = take; (int)(base + q) < PRE_K && q < (int)r; q++)
            val[base + q] = 0ull;
    }
    if (tid >= PRE_K) val[tid] = 0ull;
    __syncthreads();

    for (int k = 2; k <= 1024; k <<= 1) {
        for (int j = k >> 1; j > 0; j >>= 1) {
            int i = tid, ixj = i ^ j;
            if (ixj > i) {
                unsigned long long a = val[i], c = val[ixj];
                bool descBlock = ((i & k) == 0);
                if ((a < c) == descBlock) { val[i] = c; val[ixj] = a; }
            }
            __syncthreads();
        }
    }
    if (tid < PRE_K)
        g_topidx[b*PRE_K + tid] = 0xFFFFFFFFu - (unsigned)(val[tid] & 0xFFFFFFFFull);
}

// ---------------- decode + clip ----------------
__global__ void decode_kernel(const int* ihp, const int* iwp)
{
    const int b = blockIdx.x, j = threadIdx.x;
    if (j >= PRE_K) return;
    const float img_h = dimval(ihp);
    const float img_w = dimval(iwp);

    unsigned n = g_topidx[b*PRE_K + j];
    int a  = n % 9;
    int px = n / 9;
    int x  = px & 127, y = px >> 7;
    float sx = x * 16.0f, sy = y * 16.0f;

    float b0 = g_anch[a*4+0], b1 = g_anch[a*4+1], b2 = g_anch[a*4+2], b3 = g_anch[a*4+3];
    float ax1 = b0 + sx, ay1 = b1 + sy, ax2 = b2 + sx, ay2 = b3 + sy;
    float w = ax2 - ax1, h = ay2 - ay1;
    float cx = ax1 + 0.5f*w, cy = ay1 + 0.5f*h;

    const float* d = &g_deltas[((size_t)b*NSC + n)*4];
    float dx = d[0], dy = d[1], dw = d[2], dh = d[3];
    float pcx = cx + dx*w, pcy = cy + dy*h;
    float pw = w * expf(dw), ph = h * expf(dh);
    float x1 = pcx - 0.5f*pw, y1 = pcy - 0.5f*ph;
    float x2 = pcx + 0.5f*pw, y2 = pcy + 0.5f*ph;
    x1 = fminf(fmaxf(x1, 0.f), img_w);
    y1 = fminf(fmaxf(y1, 0.f), img_h);
    x2 = fminf(fmaxf(x2, 0.f), img_w);
    y2 = fminf(fmaxf(y2, 0.f), img_h);

    float* ob = &g_boxes[(b*PRE_K + j)*4];
    ob[0] = x1; ob[1] = y1; ob[2] = x2; ob[3] = y2;
}

// ---------------- NMS suppression bitmask ----------------
__global__ void nms_mask_kernel()
{
    const int b = blockIdx.z, cbk = blockIdx.x, rbk = blockIdx.y, t = threadIdx.x;
    __shared__ float4 colb[32];
    int j = cbk*32 + t;
    if (j < PRE_K) colb[t] = *(const float4*)&g_boxes[(b*PRE_K + j)*4];
    __syncthreads();

    int i = rbk*32 + t;
    if (i >= PRE_K) return;
    float4 bi = *(const float4*)&g_boxes[(b*PRE_K + i)*4];
    float ai = (bi.z - bi.x) * (bi.w - bi.y);
    unsigned bits = 0u;
#pragma unroll
    for (int jj = 0; jj < 32; jj++) {
        int jg = cbk*32 + jj;
        if (jg >= PRE_K) break;
        if (jg <= i) continue;
        float4 bj = colb[jj];
        float xx1 = fmaxf(bi.x, bj.x), yy1 = fmaxf(bi.y, bj.y);
        float xx2 = fminf(bi.z, bj.z), yy2 = fminf(bi.w, bj.w);
        float inter = fmaxf(xx2 - xx1, 0.f) * fmaxf(yy2 - yy1, 0.f);
        float aj = (bj.z - bj.x) * (bj.w - bj.y);
        float iou = inter / (ai + aj - inter);
        if (iou > NMS_T) bits |= (1u << jj);
    }
    g_mask[(b*PRE_K + i)*MASKW + cbk] = bits;
}

// ---------------- sequential greedy scan + emit ----------------
__global__ void final_kernel(float* __restrict__ out)
{
    const int b = blockIdx.x;
    if (threadIdx.x != 0) return;
    unsigned remv[MASKW];
#pragma unroll
    for (int w = 0; w < MASKW; w++) remv[w] = 0u;
    int nk = 0;
    for (int i = 0; i < PRE_K; i++) {
        if (!((remv[i >> 5] >> (i & 31)) & 1u)) {
            const float* bx = &g_boxes[(b*PRE_K + i)*4];
            float* o = &out[(b*POST_K + nk)*4];
            o[0] = bx[0]; o[1] = bx[1]; o[2] = bx[2]; o[3] = bx[3];
            nk++;
            if (nk >= POST_K) break;
            const unsigned* m = &g_mask[(b*PRE_K + i)*MASKW];
#pragma unroll
            for (int w = 0; w < MASKW; w++) remv[w] |= m[w];
        }
    }
    for (int k = nk; k < POST_K; k++) {
        float* o = &out[(b*POST_K + k)*4];
        o[0] = 0.f; o[1] = 0.f; o[2] = 0.f; o[3] = 0.f;
    }
}

// ---------------- launcher ----------------
extern "C" void kernel_launch(void* const* d_in, const int* in_sizes, int n_in,
                              void* d_out, int out_size)
{
    const float* feat = (const float*)d_in[0];
    const float* cw   = (const float*)d_in[1];
    const float* cb   = (const float*)d_in[2];
    const float* clw  = (const float*)d_in[3];
    const float* clb  = (const float*)d_in[4];
    const float* bw   = (const float*)d_in[5];
    const float* bb   = (const float*)d_in[6];
    const int*   ihp  = (const int*)d_in[7];
    const int*   iwp  = (const int*)d_in[8];
    float* out = (float*)d_out;

    static int smem_set = 0;
    if (!smem_set) {
        cudaFuncSetAttribute(conv_tc, cudaFuncAttributeMaxDynamicSharedMemorySize, SM_TOTAL);
        smem_set = 1;
    }

    prep_w<<<2304, 256>>>(cw);
    prep_f<<<16384, 256>>>(feat);
    prep_heads<<<49, 256>>>(clw, clb, bw, bb);
    conv_tc<<<dim3(2, 128, 4), 256, SM_TOTAL>>>(cb);
    heads_kernel<<<BATCH*NPIX/32, 256>>>();
    select_kernel<<<BATCH, 1024>>>();
    decode_kernel<<<BATCH, 640>>>(ihp, iwp);
    nms_mask_kernel<<<dim3(MASKW, MASKW, BATCH), 32>>>();
    final_kernel<<<BATCH, 32>>>(out);
}

// round 8
// speedup vs baseline: 1.2100x; 1.0069x over previous
#include <cuda_runtime.h>
#include <cuda_bf16.h>
#include <cstdint>
#include <math.h>

// ---------------- problem constants ----------------
#define BATCH 4
#define CIN   256
#define HH    128
#define WW    128
#define NANCH 9
#define NPIX  (HH*WW)         // 16384
#define NSC   (NPIX*NANCH)    // 147456 per image
#define PRE_K 600
#define POST_K 100
#define NMS_T 0.7f
#define MASKW 19              // ceil(600/32)

#define FSZ ((size_t)BATCH*NPIX*CIN)     // 16777216 elems per split
#define WSZ ((size_t)256*9*256)          // 589824 elems per split

// ---------------- device scratch (static; no allocations) ----------------
__device__ __align__(16) float g_t[(size_t)BATCH*NPIX*CIN];       // conv out NHWC
__device__ __align__(16) __nv_bfloat16 g_fs[3*FSZ];               // features NHWC, bf16 x3 splits
__device__ __align__(16) __nv_bfloat16 g_wb[3*WSZ];               // weights [s][oc][tap][ci]
__device__ __align__(16) float g_hw[CIN*48];                      // [ci][48]: 9 cls + 36 bbox + 3 pad
__device__ float g_hb[48];
__device__ __align__(16) float g_anch[NANCH*4];
__device__ float g_scores[BATCH*NSC];
__device__ __align__(16) float g_deltas[(size_t)BATCH*NSC*4];
__device__ unsigned g_topidx[BATCH*PRE_K];
__device__ __align__(16) float g_boxes[BATCH*PRE_K*4];
__device__ unsigned g_mask[BATCH*PRE_K*MASKW];

// ---------------- small helpers ----------------
__device__ __forceinline__ unsigned okey(float f) {
    unsigned u = __float_as_uint(f);
    return (u & 0x80000000u) ? ~u : (u | 0x80000000u);
}
__device__ __forceinline__ float dimval(const int* p) {
    int raw = *p;
    if (raw > 0 && raw < 1000000) return (float)raw;
    return __int_as_float(raw);
}
__device__ __forceinline__ uint32_t smem_u32(const void* p) {
    uint32_t a;
    asm("{ .reg .u64 t; cvta.to.shared.u64 t, %1; cvt.u32.u64 %0, t; }" : "=r"(a) : "l"(p));
    return a;
}

// bf16x3 split of an fp32 value
__device__ __forceinline__ void split3(float v, __nv_bfloat16& h1, __nv_bfloat16& h2, __nv_bfloat16& h3) {
    h1 = __float2bfloat16_rn(v);
    float r1 = v - __bfloat162float(h1);
    h2 = __float2bfloat16_rn(r1);
    float r2 = r1 - __bfloat162float(h2);
    h3 = __float2bfloat16_rn(r2);
}

// ---------------- prep: weight split ----------------
__global__ void prep_w(const float* __restrict__ cw)
{
    int e = blockIdx.x * 256 + threadIdx.x;
    if (e >= (int)WSZ) return;
    int oc = e / 2304; int r = e - oc*2304; int tap = r >> 8; int ci = r & 255;
    float v = cw[(oc*256 + ci)*9 + tap];
    __nv_bfloat16 h1, h2, h3; split3(v, h1, h2, h3);
    g_wb[e] = h1; g_wb[WSZ + e] = h2; g_wb[2*WSZ + e] = h3;
}

// ---------------- prep: feature NCHW fp32 -> NHWC bf16 x3 ----------------
__global__ __launch_bounds__(256) void prep_f(const float* __restrict__ feat)
{
    int bid = blockIdx.x;
    int xg = bid & 3; int cg = (bid >> 2) & 7; int y = (bid >> 5) & 127; int b = bid >> 12;
    __shared__ float ts[32][33];
    int tid = threadIdx.x;
#pragma unroll
    for (int i = 0; i < 4; i++) {
        int f = tid + i*256;
        int cc = f >> 5, xx = f & 31;
        ts[cc][xx] = feat[((size_t)((b*256 + cg*32 + cc)*128 + y) << 7) + xg*32 + xx];
    }
    __syncthreads();
#pragma unroll
    for (int i = 0; i < 4; i++) {
        int f = tid + i*256;
        int xx = f >> 5, cc = f & 31;
        float v = ts[cc][xx];
        __nv_bfloat16 h1, h2, h3; split3(v, h1, h2, h3);
        size_t o = ((size_t)((b*128 + y)*128 + xg*32 + xx))*256 + cg*32 + cc;
        g_fs[o] = h1; g_fs[FSZ + o] = h2; g_fs[2*FSZ + o] = h3;
    }
}

// ---------------- prep: head weights pack + anchors ----------------
__global__ void prep_heads(const float* __restrict__ clw, const float* __restrict__ clb,
                           const float* __restrict__ bw,  const float* __restrict__ bb)
{
    int i = blockIdx.x * 256 + threadIdx.x;
    if (i < 256*48) {
        int ci = i / 48; int o = i - ci*48;
        float v = 0.f;
        if (o < 9) v = clw[o*256 + ci];
        else if (o < 45) v = bw[(o-9)*256 + ci];
        g_hw[i] = v;
        return;
    }
    i -= 256*48;
    if (i < 48) {
        float v = 0.f;
        if (i < 9) v = clb[i]; else if (i < 45) v = bb[i-9];
        g_hb[i] = v;
        return;
    }
    i -= 48;
    if (i < 36) {
        int a = i >> 2, c = i & 3;
        int si = a / 3, ri = a - si*3;
        double sc = (si == 0) ? 8.0 : (si == 1) ? 16.0 : 32.0;
        double rt = (ri == 0) ? 0.5 : (ri == 1) ? 1.0 : 2.0;
        double w = 16.0 * sc * sqrt(rt);
        double h = 16.0 * sc / sqrt(rt);
        double v = (c == 0) ? (-w*0.5) : (c == 1) ? (-h*0.5) : (c == 2) ? (w*0.5) : (h*0.5);
        g_anch[i] = (float)v;
    }
}

// ---------------- conv 3x3 + bias + relu via mma.sync bf16x3 + cp.async ----------------
// CTA: M=128 px (one y-row) x N=64 oc; K-chunk=32 ci of one tap; 72 chunks.
// 2-stage cp.async pipeline, 1 __syncthreads per chunk, 2 CTAs/SM.
// Row stride 80B (5*16B, gcd(5,8)=1) -> conflict-free ldmatrix without swizzle.
#define ROWB   80
#define A_SPL  (128*ROWB)            // 10240 B per A split tile
#define A_SZ   (3*A_SPL)             // 30720
#define B_SPL  (64*ROWB)             // 5120 B per B split tile
#define B_SZ   (3*B_SPL)             // 15360
#define STG_SZ (A_SZ + B_SZ)         // 46080
#define NSTG   2
#define SM_TOTAL (NSTG*STG_SZ)       // 92160

#define LDMX4(r0,r1,r2,r3,addr) \
    asm volatile("ldmatrix.sync.aligned.m8n8.x4.shared.b16 {%0,%1,%2,%3}, [%4];" \
        : "=r"(r0), "=r"(r1), "=r"(r2), "=r"(r3) : "r"(addr))

#define MMA16816(d,a,b) \
    asm volatile("mma.sync.aligned.m16n8k16.row.col.f32.bf16.bf16.f32 " \
        "{%0,%1,%2,%3}, {%4,%5,%6,%7}, {%8,%9}, {%0,%1,%2,%3};" \
        : "+f"((d)[0]), "+f"((d)[1]), "+f"((d)[2]), "+f"((d)[3]) \
        : "r"((a)[0]), "r"((a)[1]), "r"((a)[2]), "r"((a)[3]), "r"((b)[0]), "r"((b)[1]))

#define CP_ASYNC16(daddr, gptr, sz) \
    asm volatile("cp.async.cg.shared.global [%0], [%1], 16, %2;" \
        :: "r"(daddr), "l"(gptr), "r"(sz))
#define CP_COMMIT() asm volatile("cp.async.commit_group;" ::: "memory")
#define CP_WAIT0()  asm volatile("cp.async.wait_group 0;" ::: "memory")

extern __shared__ char cv_smem[];

__global__ __launch_bounds__(256, 2) void conv_tc(const float* __restrict__ bias)
{
    char* smem = cv_smem;
    const uint32_t sbase = smem_u32(smem);
    const int tid  = threadIdx.x;
    const int wid  = tid >> 5;
    const int lane = tid & 31;
    const int wm   = wid & 3;        // M group (32 px)
    const int wn   = wid >> 2;       // N group (32 oc)
    const int oc0  = blockIdx.x * 64;
    const int y    = blockIdx.y;
    const int b    = blockIdx.z;

    float acc[2][4][4];
#pragma unroll
    for (int mt = 0; mt < 2; mt++)
#pragma unroll
        for (int nt = 0; nt < 4; nt++)
#pragma unroll
            for (int q = 0; q < 4; q++) acc[mt][nt][q] = 0.f;

    // per stage: A = 1536 x 16B copies, B = 768 x 16B copies -> 9 per thread
    auto issue_stage = [&](int kc) {
        const int st = kc & 1;
        const int tap = kc >> 3, ci0 = (kc & 7) << 5;
        const int ky = tap / 3, kx = tap - ky*3;
        const int yy = y + ky - 1;
        const bool vy = ((unsigned)yy < 128u);
#pragma unroll
        for (int i = 0; i < 9; i++) {
            int v = tid + i*256;              // 0..2303
            if (v < 1536) {
                int s = v >> 9;
                int r2 = v & 511;
                int row = r2 >> 2;
                int c   = r2 & 3;
                uint32_t daddr = sbase + st*STG_SZ + s*A_SPL + row*ROWB + c*16;
                int xx = row + kx - 1;
                bool ok = vy && ((unsigned)xx < 128u);
                const __nv_bfloat16* gp = ok
                    ? g_fs + (size_t)s*FSZ + ((size_t)((b*128 + yy)*128 + xx))*256 + ci0 + c*8
                    : g_fs;                   // dummy valid address; sz=0 -> zero-fill
                CP_ASYNC16(daddr, gp, ok ? 16 : 0);
            } else {
                int r = v - 1536;             // 0..767
                int s = r >> 8;
                int r2 = r & 255;
                int row = r2 >> 2;
                int c   = r2 & 3;
                uint32_t daddr = sbase + st*STG_SZ + A_SZ + s*B_SPL + row*ROWB + c*16;
                const __nv_bfloat16* gp = g_wb + (size_t)s*WSZ + ((size_t)((oc0 + row)*9 + tap))*256 + ci0 + c*8;
                CP_ASYNC16(daddr, gp, 16);
            }
        }
        CP_COMMIT();
    };

    auto compute = [&](int st) {
        const uint32_t abase = sbase + st*STG_SZ;
        const uint32_t bbase = abase + A_SZ;
#pragma unroll
        for (int h = 0; h < 2; h++) {
            uint32_t colo = h*32 + ((lane >> 4) << 4);
            uint32_t afr[3][2][4];
#pragma unroll
            for (int s = 0; s < 3; s++) {
#pragma unroll
                for (int mt = 0; mt < 2; mt++) {
                    uint32_t addr = abase + s*A_SPL + (wm*32 + mt*16 + (lane & 15))*ROWB + colo;
                    LDMX4(afr[s][mt][0], afr[s][mt][1], afr[s][mt][2], afr[s][mt][3], addr);
                }
            }
#pragma unroll
            for (int sb = 0; sb < 3; sb++) {
                uint32_t bfr[4][2];
#pragma unroll
                for (int p = 0; p < 2; p++) {
                    uint32_t r0, r1, r2, r3;
                    uint32_t addr = bbase + sb*B_SPL + (wn*32 + p*16 + (lane & 15))*ROWB + colo;
                    LDMX4(r0, r1, r2, r3, addr);
                    bfr[2*p][0] = r0;   bfr[2*p][1] = r2;
                    bfr[2*p+1][0] = r1; bfr[2*p+1][1] = r3;
                }
                int nA = (sb == 0) ? 3 : (sb == 1) ? 2 : 1;
#pragma unroll
                for (int sa = 0; sa < 3; sa++) {
                    if (sa >= nA) break;
#pragma unroll
                    for (int mt = 0; mt < 2; mt++)
#pragma unroll
                        for (int nt = 0; nt < 4; nt++)
                            MMA16816(acc[mt][nt], afr[sa][mt], bfr[nt]);
                }
            }
        }
    };

    const int NCH = 72;
    issue_stage(0);
#pragma unroll 1
    for (int c = 0; c < NCH; c++) {
        CP_WAIT0();
        __syncthreads();
        if (c + 1 < NCH) issue_stage(c + 1);
        compute(c & 1);
    }

    // epilogue: bias + relu, direct float2 stores to NHWC g_t
    const int gid = lane >> 2, tg = lane & 3;
    float* base = g_t + ((size_t)((b*128 + y)*128))*256 + oc0;
#pragma unroll
    for (int mt = 0; mt < 2; mt++) {
#pragma unroll
        for (int nt = 0; nt < 4; nt++) {
            int col = wn*32 + nt*8 + tg*2;
            float b0 = __ldg(&bias[oc0 + col]);
            float b1 = __ldg(&bias[oc0 + col + 1]);
            int px0 = wm*32 + mt*16 + gid;
            float2 v0, v1;
            v0.x = fmaxf(acc[mt][nt][0] + b0, 0.f);
            v0.y = fmaxf(acc[mt][nt][1] + b1, 0.f);
            v1.x = fmaxf(acc[mt][nt][2] + b0, 0.f);
            v1.y = fmaxf(acc[mt][nt][3] + b1, 0.f);
            *(float2*)(base + (size_t)px0*256 + col)       = v0;
            *(float2*)(base + (size_t)(px0 + 8)*256 + col) = v1;
        }
    }
}

// ---------------- heads: per 32-pixel tile, 48 outputs ----------------
__global__ __launch_bounds__(256) void heads_kernel()
{
    __shared__ float ts[32][257];
    const int pxg0 = blockIdx.x * 32;
    const int tid  = threadIdx.x;

#pragma unroll
    for (int i = 0; i < 8; i++) {
        int f = tid + i*256;
        int px = f >> 6;
        int q  = f & 63;
        float4 v = *(const float4*)&g_t[((size_t)(pxg0 + px))*256 + q*4];
        ts[px][q*4+0] = v.x; ts[px][q*4+1] = v.y;
        ts[px][q*4+2] = v.z; ts[px][q*4+3] = v.w;
    }
    __syncthreads();

    const int px = tid & 31;
    const int ob = tid >> 5;
    const int pxg = pxg0 + px;
    const int b   = pxg >> 14;
    const int pxi = pxg & 16383;

#pragma unroll 1
    for (int c = 0; c < 6; c++) {
        int o = ob*6 + c;
        float acc = g_hb[o];
#pragma unroll 8
        for (int k = 0; k < 256; k++)
            acc += ts[px][k] * __ldg(&g_hw[k*48 + o]);
        if (o < 9) {
            g_scores[(size_t)b*NSC + pxi*9 + o] = acc;
        } else if (o < 45) {
            int q = o - 9;
            g_deltas[((size_t)b*NSC + pxi*9 + (q >> 2))*4 + (q & 3)] = acc;
        }
    }
}

// ---------------- exact top-600 per image: radix select + bitonic sort ----------------
__global__ __launch_bounds__(1024) void select_kernel()
{
    const int b   = blockIdx.x;
    const int tid = threadIdx.x;
    const float* sc = g_scores + (size_t)b * NSC;

    __shared__ unsigned hist[256];
    __shared__ unsigned sh_prefix, sh_want, sh_cntG, sh_cntE;
    __shared__ unsigned eqi[512];
    __shared__ unsigned long long val[1024];

    if (tid == 0) { sh_prefix = 0u; sh_want = PRE_K; sh_cntG = 0u; sh_cntE = 0u; }

    for (int p = 3; p >= 0; --p) {
        if (tid < 256) hist[tid] = 0u;
        __syncthreads();
        unsigned hm   = (p == 3) ? 0u : (0xFFFFFFFFu << ((p + 1) * 8));
        unsigned pref = sh_prefix;
        for (int n = tid; n < NSC; n += 1024) {
            unsigned k = okey(sc[n]);
            if ((k & hm) == pref) atomicAdd(&hist[(k >> (p * 8)) & 255], 1u);
        }
        __syncthreads();
        if (tid == 0) {
            unsigned want = sh_want, cum = 0; int chosen = 0;
            for (int bin = 255; bin >= 0; --bin) {
                unsigned c = hist[bin];
                if (cum + c >= want) { chosen = bin; break; }
                cum += c;
            }
            sh_want   = want - cum;
            sh_prefix = pref | ((unsigned)chosen << (p * 8));
        }
        __syncthreads();
    }
    const unsigned T = sh_prefix;
    const unsigned r = sh_want;

    for (int n = tid; n < NSC; n += 1024) {
        unsigned k = okey(sc[n]);
        if (k > T) {
            unsigned pos = atomicAdd(&sh_cntG, 1u);
            val[pos] = (((unsigned long long)k) << 32) | (unsigned long long)(0xFFFFFFFFu - (unsigned)n);
        } else if (k == T) {
            unsigned pos = atomicAdd(&sh_cntE, 1u);
            if (pos < 512) eqi[pos] = (unsigned)n;
        }
    }
    __syncthreads();
    if (tid == 0) {
        int ne = (sh_cntE < 512u) ? (int)sh_cntE : 512;
        for (int a2 = 1; a2 < ne; a2++) {
            unsigned v = eqi[a2]; int b2 = a2 - 1;
            while (b2 >= 0 && eqi[b2] > v) { eqi[b2+1] = eqi[b2]; b2--; }
            eqi[b2+1] = v;
        }
        int take = ((int)r < ne) ? (int)r : ne;
        unsigned base = sh_cntG;
        for (int q = 0; q < take; q++)
            val[base + q] = (((unsigned long long)T) << 32) | (unsigned long long)(0xFFFFFFFFu - eqi[q]);
        for (int q = take; (int)(base + q) < PRE_K && q < (int)r; q++)
            val[base + q] = 0ull;
    }
    if (tid >= PRE_K) val[tid] = 0ull;
    __syncthreads();

    for (int k = 2; k <= 1024; k <<= 1) {
        for (int j = k >> 1; j > 0; j >>= 1) {
            int i = tid, ixj = i ^ j;
            if (ixj > i) {
                unsigned long long a = val[i], c = val[ixj];
                bool descBlock = ((i & k) == 0);
                if ((a < c) == descBlock) { val[i] = c; val[ixj] = a; }
            }
            __syncthreads();
        }
    }
    if (tid < PRE_K)
        g_topidx[b*PRE_K + tid] = 0xFFFFFFFFu - (unsigned)(val[tid] & 0xFFFFFFFFull);
}

// ---------------- decode + clip ----------------
__global__ void decode_kernel(const int* ihp, const int* iwp)
{
    const int b = blockIdx.x, j = threadIdx.x;
    if (j >= PRE_K) return;
    const float img_h = dimval(ihp);
    const float img_w = dimval(iwp);

    unsigned n = g_topidx[b*PRE_K + j];
    int a  = n % 9;
    int px = n / 9;
    int x  = px & 127, y = px >> 7;
    float sx = x * 16.0f, sy = y * 16.0f;

    float b0 = g_anch[a*4+0], b1 = g_anch[a*4+1], b2 = g_anch[a*4+2], b3 = g_anch[a*4+3];
    float ax1 = b0 + sx, ay1 = b1 + sy, ax2 = b2 + sx, ay2 = b3 + sy;
    float w = ax2 - ax1, h = ay2 - ay1;
    float cx = ax1 + 0.5f*w, cy = ay1 + 0.5f*h;

    const float* d = &g_deltas[((size_t)b*NSC + n)*4];
    float dx = d[0], dy = d[1], dw = d[2], dh = d[3];
    float pcx = cx + dx*w, pcy = cy + dy*h;
    float pw = w * expf(dw), ph = h * expf(dh);
    float x1 = pcx - 0.5f*pw, y1 = pcy - 0.5f*ph;
    float x2 = pcx + 0.5f*pw, y2 = pcy + 0.5f*ph;
    x1 = fminf(fmaxf(x1, 0.f), img_w);
    y1 = fminf(fmaxf(y1, 0.f), img_h);
    x2 = fminf(fmaxf(x2, 0.f), img_w);
    y2 = fminf(fmaxf(y2, 0.f), img_h);

    float* ob = &g_boxes[(b*PRE_K + j)*4];
    ob[0] = x1; ob[1] = y1; ob[2] = x2; ob[3] = y2;
}

// ---------------- NMS suppression bitmask ----------------
__global__ void nms_mask_kernel()
{
    const int b = blockIdx.z, cbk = blockIdx.x, rbk = blockIdx.y, t = threadIdx.x;
    __shared__ float4 colb[32];
    int j = cbk*32 + t;
    if (j < PRE_K) colb[t] = *(const float4*)&g_boxes[(b*PRE_K + j)*4];
    __syncthreads();

    int i = rbk*32 + t;
    if (i >= PRE_K) return;
    float4 bi = *(const float4*)&g_boxes[(b*PRE_K + i)*4];
    float ai = (bi.z - bi.x) * (bi.w - bi.y);
    unsigned bits = 0u;
#pragma unroll
    for (int jj = 0; jj < 32; jj++) {
        int jg = cbk*32 + jj;
        if (jg >= PRE_K) break;
        if (jg <= i) continue;
        float4 bj = colb[jj];
        float xx1 = fmaxf(bi.x, bj.x), yy1 = fmaxf(bi.y, bj.y);
        float xx2 = fminf(bi.z, bj.z), yy2 = fminf(bi.w, bj.w);
        float inter = fmaxf(xx2 - xx1, 0.f) * fmaxf(yy2 - yy1, 0.f);
        float aj = (bj.z - bj.x) * (bj.w - bj.y);
        float iou = inter / (ai + aj - inter);
        if (iou > NMS_T) bits |= (1u << jj);
    }
    g_mask[(b*PRE_K + i)*MASKW + cbk] = bits;
}

// ---------------- sequential greedy scan + emit ----------------
__global__ void final_kernel(float* __restrict__ out)
{
    const int b = blockIdx.x;
    if (threadIdx.x != 0) return;
    unsigned remv[MASKW];
#pragma unroll
    for (int w = 0; w < MASKW; w++) remv[w] = 0u;
    int nk = 0;
    for (int i = 0; i < PRE_K; i++) {
        if (!((remv[i >> 5] >> (i & 31)) & 1u)) {
            const float* bx = &g_boxes[(b*PRE_K + i)*4];
            float* o = &out[(b*POST_K + nk)*4];
            o[0] = bx[0]; o[1] = bx[1]; o[2] = bx[2]; o[3] = bx[3];
            nk++;
            if (nk >= POST_K) break;
            const unsigned* m = &g_mask[(b*PRE_K + i)*MASKW];
#pragma unroll
            for (int w = 0; w < MASKW; w++) remv[w] |= m[w];
        }
    }
    for (int k = nk; k < POST_K; k++) {
        float* o = &out[(b*POST_K + k)*4];
        o[0] = 0.f; o[1] = 0.f; o[2] = 0.f; o[3] = 0.f;
    }
}

// ---------------- launcher ----------------
extern "C" void kernel_launch(void* const* d_in, const int* in_sizes, int n_in,
                              void* d_out, int out_size)
{
    const float* feat = (const float*)d_in[0];
    const float* cw   = (const float*)d_in[1];
    const float* cb   = (const float*)d_in[2];
    const float* clw  = (const float*)d_in[3];
    const float* clb  = (const float*)d_in[4];
    const float* bw   = (const float*)d_in[5];
    const float* bb   = (const float*)d_in[6];
    const int*   ihp  = (const int*)d_in[7];
    const int*   iwp  = (const int*)d_in[8];
    float* out = (float*)d_out;

    static int smem_set = 0;
    if (!smem_set) {
        cudaFuncSetAttribute(conv_tc, cudaFuncAttributeMaxDynamicSharedMemorySize, SM_TOTAL);
        smem_set = 1;
    }

    prep_w<<<2304, 256>>>(cw);
    prep_f<<<16384, 256>>>(feat);
    prep_heads<<<49, 256>>>(clw, clb, bw, bb);
    conv_tc<<<dim3(4, 128, 4), 256, SM_TOTAL>>>(cb);
    heads_kernel<<<BATCH*NPIX/32, 256>>>();
    select_kernel<<<BATCH, 1024>>>();
    decode_kernel<<<BATCH, 640>>>(ihp, iwp);
    nms_mask_kernel<<<dim3(MASKW, MASKW, BATCH), 32>>>();
    final_kernel<<<BATCH, 32>>>(out);
}

// round 10
// speedup vs baseline: 1.8330x; 1.5149x over previous
#include <cuda_runtime.h>
#include <cuda_bf16.h>
#include <cstdint>
#include <math.h>

// ---------------- problem constants ----------------
#define BATCH 4
#define CIN   256
#define HH    128
#define WW    128
#define NANCH 9
#define NPIX  (HH*WW)         // 16384
#define NSC   (NPIX*NANCH)    // 147456 per image
#define PRE_K 600
#define POST_K 100
#define NMS_T 0.7f
#define MASKW 19              // ceil(600/32)

#define FSZ ((size_t)BATCH*NPIX*CIN)     // 16777216 elems per split
#define WSZ ((size_t)256*9*256)          // 589824 elems per split

// ---------------- device scratch (static; no allocations) ----------------
__device__ __align__(16) float g_t[(size_t)BATCH*NPIX*CIN];       // conv out NHWC
__device__ __align__(16) __nv_bfloat16 g_fs[2*FSZ];               // features NHWC, bf16 x2 splits
__device__ __align__(16) __nv_bfloat16 g_wb[2*WSZ];               // weights [s][oc][tap][ci]
__device__ __align__(16) float g_hw[CIN*48];                      // [ci][48]: 9 cls + 36 bbox + 3 pad
__device__ float g_hb[48];
__device__ __align__(16) float g_anch[NANCH*4];
__device__ float g_scores[BATCH*NSC];
__device__ __align__(16) float g_deltas[(size_t)BATCH*NSC*4];
__device__ unsigned g_topidx[BATCH*PRE_K];
__device__ __align__(16) float g_boxes[BATCH*PRE_K*4];
__device__ unsigned g_mask[BATCH*PRE_K*MASKW];

// ---------------- small helpers ----------------
__device__ __forceinline__ unsigned okey(float f) {
    unsigned u = __float_as_uint(f);
    return (u & 0x80000000u) ? ~u : (u | 0x80000000u);
}
__device__ __forceinline__ float dimval(const int* p) {
    int raw = *p;
    if (raw > 0 && raw < 1000000) return (float)raw;
    return __int_as_float(raw);
}
__device__ __forceinline__ uint32_t smem_u32(const void* p) {
    uint32_t a;
    asm("{ .reg .u64 t; cvta.to.shared.u64 t, %1; cvt.u32.u64 %0, t; }" : "=r"(a) : "l"(p));
    return a;
}

// bf16x2 split of an fp32 value
__device__ __forceinline__ void split2(float v, __nv_bfloat16& h1, __nv_bfloat16& h2) {
    h1 = __float2bfloat16_rn(v);
    h2 = __float2bfloat16_rn(v - __bfloat162float(h1));
}

// ---------------- prep: weight split ----------------
__global__ void prep_w(const float* __restrict__ cw)
{
    int e = blockIdx.x * 256 + threadIdx.x;
    if (e >= (int)WSZ) return;
    int oc = e / 2304; int r = e - oc*2304; int tap = r >> 8; int ci = r & 255;
    float v = cw[(oc*256 + ci)*9 + tap];
    __nv_bfloat16 h1, h2; split2(v, h1, h2);
    g_wb[e] = h1; g_wb[WSZ + e] = h2;
}

// ---------------- prep: feature NCHW fp32 -> NHWC bf16 x2 ----------------
__global__ __launch_bounds__(256) void prep_f(const float* __restrict__ feat)
{
    int bid = blockIdx.x;
    int xg = bid & 3; int cg = (bid >> 2) & 7; int y = (bid >> 5) & 127; int b = bid >> 12;
    __shared__ float ts[32][33];
    int tid = threadIdx.x;
#pragma unroll
    for (int i = 0; i < 4; i++) {
        int f = tid + i*256;
        int cc = f >> 5, xx = f & 31;
        ts[cc][xx] = feat[((size_t)((b*256 + cg*32 + cc)*128 + y) << 7) + xg*32 + xx];
    }
    __syncthreads();
#pragma unroll
    for (int i = 0; i < 4; i++) {
        int f = tid + i*256;
        int xx = f >> 5, cc = f & 31;
        float v = ts[cc][xx];
        __nv_bfloat16 h1, h2; split2(v, h1, h2);
        size_t o = ((size_t)((b*128 + y)*128 + xg*32 + xx))*256 + cg*32 + cc;
        g_fs[o] = h1; g_fs[FSZ + o] = h2;
    }
}

// ---------------- prep: head weights pack + anchors ----------------
__global__ void prep_heads(const float* __restrict__ clw, const float* __restrict__ clb,
                           const float* __restrict__ bw,  const float* __restrict__ bb)
{
    int i = blockIdx.x * 256 + threadIdx.x;
    if (i < 256*48) {
        int ci = i / 48; int o = i - ci*48;
        float v = 0.f;
        if (o < 9) v = clw[o*256 + ci];
        else if (o < 45) v = bw[(o-9)*256 + ci];
        g_hw[i] = v;
        return;
    }
    i -= 256*48;
    if (i < 48) {
        float v = 0.f;
        if (i < 9) v = clb[i]; else if (i < 45) v = bb[i-9];
        g_hb[i] = v;
        return;
    }
    i -= 48;
    if (i < 36) {
        int a = i >> 2, c = i & 3;
        int si = a / 3, ri = a - si*3;
        double sc = (si == 0) ? 8.0 : (si == 1) ? 16.0 : 32.0;
        double rt = (ri == 0) ? 0.5 : (ri == 1) ? 1.0 : 2.0;
        double w = 16.0 * sc * sqrt(rt);
        double h = 16.0 * sc / sqrt(rt);
        double v = (c == 0) ? (-w*0.5) : (c == 1) ? (-h*0.5) : (c == 2) ? (w*0.5) : (h*0.5);
        g_anch[i] = (float)v;
    }
}

// ---------------- conv 3x3 + bias + relu via mma.sync bf16x2 + cp.async ----------------
// CTA: M=128 px (one y-row) x N=64 oc; K-chunk=32 ci of one tap; 72 chunks.
// 3 cross-terms: a1b1, a1b2, a2b1 (a2b2 ~ 2^-18, dropped).
// 2-stage cp.async pipeline, 1 __syncthreads per chunk, 2 CTAs/SM.
// Row stride 80B (5*16B, gcd(5,8)=1) -> conflict-free ldmatrix without swizzle.
#define ROWB   80
#define A_SPL  (128*ROWB)            // 10240 B per A split tile
#define A_SZ   (2*A_SPL)             // 20480
#define B_SPL  (64*ROWB)             // 5120 B per B split tile
#define B_SZ   (2*B_SPL)             // 10240
#define STG_SZ (A_SZ + B_SZ)         // 30720
#define NSTG   2
#define SM_TOTAL (NSTG*STG_SZ)       // 61440

#define LDMX4(r0,r1,r2,r3,addr) \
    asm volatile("ldmatrix.sync.aligned.m8n8.x4.shared.b16 {%0,%1,%2,%3}, [%4];" \
        : "=r"(r0), "=r"(r1), "=r"(r2), "=r"(r3) : "r"(addr))

#define MMA16816(d,a,b) \
    asm volatile("mma.sync.aligned.m16n8k16.row.col.f32.bf16.bf16.f32 " \
        "{%0,%1,%2,%3}, {%4,%5,%6,%7}, {%8,%9}, {%0,%1,%2,%3};" \
        : "+f"((d)[0]), "+f"((d)[1]), "+f"((d)[2]), "+f"((d)[3]) \
        : "r"((a)[0]), "r"((a)[1]), "r"((a)[2]), "r"((a)[3]), "r"((b)[0]), "r"((b)[1]))

#define CP_ASYNC16(daddr, gptr, sz) \
    asm volatile("cp.async.cg.shared.global [%0], [%1], 16, %2;" \
        :: "r"(daddr), "l"(gptr), "r"(sz))
#define CP_COMMIT() asm volatile("cp.async.commit_group;" ::: "memory")
#define CP_WAIT0()  asm volatile("cp.async.wait_group 0;" ::: "memory")

extern __shared__ char cv_smem[];

__global__ __launch_bounds__(256, 2) void conv_tc(const float* __restrict__ bias)
{
    char* smem = cv_smem;
    const uint32_t sbase = smem_u32(smem);
    const int tid  = threadIdx.x;
    const int wid  = tid >> 5;
    const int lane = tid & 31;
    const int wm   = wid & 3;        // M group (32 px)
    const int wn   = wid >> 2;       // N group (32 oc)
    const int oc0  = blockIdx.x * 64;
    const int y    = blockIdx.y;
    const int b    = blockIdx.z;

    float acc[2][4][4];
#pragma unroll
    for (int mt = 0; mt < 2; mt++)
#pragma unroll
        for (int nt = 0; nt < 4; nt++)
#pragma unroll
            for (int q = 0; q < 4; q++) acc[mt][nt][q] = 0.f;

    // per stage: A = 1024 x 16B copies, B = 512 x 16B copies -> 6 per thread
    auto issue_stage = [&](int kc) {
        const int st = kc & 1;
        const int tap = kc >> 3, ci0 = (kc & 7) << 5;
        const int ky = tap / 3, kx = tap - ky*3;
        const int yy = y + ky - 1;
        const bool vy = ((unsigned)yy < 128u);
#pragma unroll
        for (int i = 0; i < 6; i++) {
            int v = tid + i*256;              // 0..1535
            if (v < 1024) {
                int s = v >> 9;
                int r2 = v & 511;
                int row = r2 >> 2;
                int c   = r2 & 3;
                uint32_t daddr = sbase + st*STG_SZ + s*A_SPL + row*ROWB + c*16;
                int xx = row + kx - 1;
                bool ok = vy && ((unsigned)xx < 128u);
                const __nv_bfloat16* gp = ok
                    ? g_fs + (size_t)s*FSZ + ((size_t)((b*128 + yy)*128 + xx))*256 + ci0 + c*8
                    : g_fs;                   // dummy valid address; sz=0 -> zero-fill
                CP_ASYNC16(daddr, gp, ok ? 16 : 0);
            } else {
                int r = v - 1024;             // 0..511
                int s = r >> 8;
                int r2 = r & 255;
                int row = r2 >> 2;
                int c   = r2 & 3;
                uint32_t daddr = sbase + st*STG_SZ + A_SZ + s*B_SPL + row*ROWB + c*16;
                const __nv_bfloat16* gp = g_wb + (size_t)s*WSZ + ((size_t)((oc0 + row)*9 + tap))*256 + ci0 + c*8;
                CP_ASYNC16(daddr, gp, 16);
            }
        }
        CP_COMMIT();
    };

    auto compute = [&](int st) {
        const uint32_t abase = sbase + st*STG_SZ;
        const uint32_t bbase = abase + A_SZ;
#pragma unroll
        for (int h = 0; h < 2; h++) {
            uint32_t colo = h*32 + ((lane >> 4) << 4);
            uint32_t afr[2][2][4];
#pragma unroll
            for (int s = 0; s < 2; s++) {
#pragma unroll
                for (int mt = 0; mt < 2; mt++) {
                    uint32_t addr = abase + s*A_SPL + (wm*32 + mt*16 + (lane & 15))*ROWB + colo;
                    LDMX4(afr[s][mt][0], afr[s][mt][1], afr[s][mt][2], afr[s][mt][3], addr);
                }
            }
#pragma unroll
            for (int sb = 0; sb < 2; sb++) {
                uint32_t bfr[4][2];
#pragma unroll
                for (int p = 0; p < 2; p++) {
                    uint32_t r0, r1, r2, r3;
                    uint32_t addr = bbase + sb*B_SPL + (wn*32 + p*16 + (lane & 15))*ROWB + colo;
                    LDMX4(r0, r1, r2, r3, addr);
                    bfr[2*p][0] = r0;   bfr[2*p][1] = r2;
                    bfr[2*p+1][0] = r1; bfr[2*p+1][1] = r3;
                }
                int nA = (sb == 0) ? 2 : 1;    // a1b1,a2b1 ; a1b2
#pragma unroll
                for (int sa = 0; sa < 2; sa++) {
                    if (sa >= nA) break;
#pragma unroll
                    for (int mt = 0; mt < 2; mt++)
#pragma unroll
                        for (int nt = 0; nt < 4; nt++)
                            MMA16816(acc[mt][nt], afr[sa][mt], bfr[nt]);
                }
            }
        }
    };

    const int NCH = 72;
    issue_stage(0);
#pragma unroll 1
    for (int c = 0; c < NCH; c++) {
        CP_WAIT0();
        __syncthreads();
        if (c + 1 < NCH) issue_stage(c + 1);
        compute(c & 1);
    }

    // epilogue: bias + relu, direct float2 stores to NHWC g_t
    const int gid = lane >> 2, tg = lane & 3;
    float* base = g_t + ((size_t)((b*128 + y)*128))*256 + oc0;
#pragma unroll
    for (int mt = 0; mt < 2; mt++) {
#pragma unroll
        for (int nt = 0; nt < 4; nt++) {
            int col = wn*32 + nt*8 + tg*2;
            float b0 = __ldg(&bias[oc0 + col]);
            float b1 = __ldg(&bias[oc0 + col + 1]);
            int px0 = wm*32 + mt*16 + gid;
            float2 v0, v1;
            v0.x = fmaxf(acc[mt][nt][0] + b0, 0.f);
            v0.y = fmaxf(acc[mt][nt][1] + b1, 0.f);
            v1.x = fmaxf(acc[mt][nt][2] + b0, 0.f);
            v1.y = fmaxf(acc[mt][nt][3] + b1, 0.f);
            *(float2*)(base + (size_t)px0*256 + col)       = v0;
            *(float2*)(base + (size_t)(px0 + 8)*256 + col) = v1;
        }
    }
}

// ---------------- heads: per 32-pixel tile, 48 outputs ----------------
__global__ __launch_bounds__(256) void heads_kernel()
{
    __shared__ float ts[32][257];
    const int pxg0 = blockIdx.x * 32;
    const int tid  = threadIdx.x;

#pragma unroll
    for (int i = 0; i < 8; i++) {
        int f = tid + i*256;
        int px = f >> 6;
        int q  = f & 63;
        float4 v = *(const float4*)&g_t[((size_t)(pxg0 + px))*256 + q*4];
        ts[px][q*4+0] = v.x; ts[px][q*4+1] = v.y;
        ts[px][q*4+2] = v.z; ts[px][q*4+3] = v.w;
    }
    __syncthreads();

    const int px = tid & 31;
    const int ob = tid >> 5;
    const int pxg = pxg0 + px;
    const int b   = pxg >> 14;
    const int pxi = pxg & 16383;

#pragma unroll 1
    for (int c = 0; c < 6; c++) {
        int o = ob*6 + c;
        float acc = g_hb[o];
#pragma unroll 8
        for (int k = 0; k < 256; k++)
            acc += ts[px][k] * __ldg(&g_hw[k*48 + o]);
        if (o < 9) {
            g_scores[(size_t)b*NSC + pxi*9 + o] = acc;
        } else if (o < 45) {
            int q = o - 9;
            g_deltas[((size_t)b*NSC + pxi*9 + (q >> 2))*4 + (q & 3)] = acc;
        }
    }
}

// ---------------- exact top-600 per image: radix select + bitonic sort ----------------
__global__ __launch_bounds__(1024) void select_kernel()
{
    const int b   = blockIdx.x;
    const int tid = threadIdx.x;
    const float* sc = g_scores + (size_t)b * NSC;

    __shared__ unsigned hist[256];
    __shared__ unsigned sh_prefix, sh_want, sh_cntG, sh_cntE;
    __shared__ unsigned eqi[512];
    __shared__ unsigned long long val[1024];

    if (tid == 0) { sh_prefix = 0u; sh_want = PRE_K; sh_cntG = 0u; sh_cntE = 0u; }

    for (int p = 3; p >= 0; --p) {
        if (tid < 256) hist[tid] = 0u;
        __syncthreads();
        unsigned hm   = (p == 3) ? 0u : (0xFFFFFFFFu << ((p + 1) * 8));
        unsigned pref = sh_prefix;
        for (int n = tid; n < NSC; n += 1024) {
            unsigned k = okey(sc[n]);
            if ((k & hm) == pref) atomicAdd(&hist[(k >> (p * 8)) & 255], 1u);
        }
        __syncthreads();
        if (tid == 0) {
            unsigned want = sh_want, cum = 0; int chosen = 0;
            for (int bin = 255; bin >= 0; --bin) {
                unsigned c = hist[bin];
                if (cum + c >= want) { chosen = bin; break; }
                cum += c;
            }
            sh_want   = want - cum;
            sh_prefix = pref | ((unsigned)chosen << (p * 8));
        }
        __syncthreads();
    }
    const unsigned T = sh_prefix;
    const unsigned r = sh_want;

    for (int n = tid; n < NSC; n += 1024) {
        unsigned k = okey(sc[n]);
        if (k > T) {
            unsigned pos = atomicAdd(&sh_cntG, 1u);
            val[pos] = (((unsigned long long)k) << 32) | (unsigned long long)(0xFFFFFFFFu - (unsigned)n);
        } else if (k == T) {
            unsigned pos = atomicAdd(&sh_cntE, 1u);
            if (pos < 512) eqi[pos] = (unsigned)n;
        }
    }
    __syncthreads();
    if (tid == 0) {
        int ne = (sh_cntE < 512u) ? (int)sh_cntE : 512;
        for (int a2 = 1; a2 < ne; a2++) {
            unsigned v = eqi[a2]; int b2 = a2 - 1;
            while (b2 >= 0 && eqi[b2] > v) { eqi[b2+1] = eqi[b2]; b2--; }
            eqi[b2+1] = v;
        }
        int take = ((int)r < ne) ? (int)r : ne;
        unsigned base = sh_cntG;
        for (int q = 0; q < take; q++)
            val[base + q] = (((unsigned long long)T) << 32) | (unsigned long long)(0xFFFFFFFFu - eqi[q]);
        for (int q = take; (int)(base + q) < PRE_K && q < (int)r; q++)
            val[base + q] = 0ull;
    }
    if (tid >= PRE_K) val[tid] = 0ull;
    __syncthreads();

    for (int k = 2; k <= 1024; k <<= 1) {
        for (int j = k >> 1; j > 0; j >>= 1) {
            int i = tid, ixj = i ^ j;
            if (ixj > i) {
                unsigned long long a = val[i], c = val[ixj];
                bool descBlock = ((i & k) == 0);
                if ((a < c) == descBlock) { val[i] = c; val[ixj] = a; }
            }
            __syncthreads();
        }
    }
    if (tid < PRE_K)
        g_topidx[b*PRE_K + tid] = 0xFFFFFFFFu - (unsigned)(val[tid] & 0xFFFFFFFFull);
}

// ---------------- decode + clip ----------------
__global__ void decode_kernel(const int* ihp, const int* iwp)
{
    const int b = blockIdx.x, j = threadIdx.x;
    if (j >= PRE_K) return;
    const float img_h = dimval(ihp);
    const float img_w = dimval(iwp);

    unsigned n = g_topidx[b*PRE_K + j];
    int a  = n % 9;
    int px = n / 9;
    int x  = px & 127, y = px >> 7;
    float sx = x * 16.0f, sy = y * 16.0f;

    float b0 = g_anch[a*4+0], b1 = g_anch[a*4+1], b2 = g_anch[a*4+2], b3 = g_anch[a*4+3];
    float ax1 = b0 + sx, ay1 = b1 + sy, ax2 = b2 + sx, ay2 = b3 + sy;
    float w = ax2 - ax1, h = ay2 - ay1;
    float cx = ax1 + 0.5f*w, cy = ay1 + 0.5f*h;

    const float* d = &g_deltas[((size_t)b*NSC + n)*4];
    float dx = d[0], dy = d[1], dw = d[2], dh = d[3];
    float pcx = cx + dx*w, pcy = cy + dy*h;
    float pw = w * expf(dw), ph = h * expf(dh);
    float x1 = pcx - 0.5f*pw, y1 = pcy - 0.5f*ph;
    float x2 = pcx + 0.5f*pw, y2 = pcy + 0.5f*ph;
    x1 = fminf(fmaxf(x1, 0.f), img_w);
    y1 = fminf(fmaxf(y1, 0.f), img_h);
    x2 = fminf(fmaxf(x2, 0.f), img_w);
    y2 = fminf(fmaxf(y2, 0.f), img_h);

    float* ob = &g_boxes[(b*PRE_K + j)*4];
    ob[0] = x1; ob[1] = y1; ob[2] = x2; ob[3] = y2;
}

// ---------------- NMS suppression bitmask ----------------
__global__ void nms_mask_kernel()
{
    const int b = blockIdx.z, cbk = blockIdx.x, rbk = blockIdx.y, t = threadIdx.x;
    __shared__ float4 colb[32];
    int j = cbk*32 + t;
    if (j < PRE_K) colb[t] = *(const float4*)&g_boxes[(b*PRE_K + j)*4];
    __syncthreads();

    int i = rbk*32 + t;
    if (i >= PRE_K) return;
    float4 bi = *(const float4*)&g_boxes[(b*PRE_K + i)*4];
    float ai = (bi.z - bi.x) * (bi.w - bi.y);
    unsigned bits = 0u;
#pragma unroll
    for (int jj = 0; jj < 32; jj++) {
        int jg = cbk*32 + jj;
        if (jg >= PRE_K) break;
        if (jg <= i) continue;
        float4 bj = colb[jj];
        float xx1 = fmaxf(bi.x, bj.x), yy1 = fmaxf(bi.y, bj.y);
        float xx2 = fminf(bi.z, bj.z), yy2 = fminf(bi.w, bj.w);
        float inter = fmaxf(xx2 - xx1, 0.f) * fmaxf(yy2 - yy1, 0.f);
        float aj = (bj.z - bj.x) * (bj.w - bj.y);
        float iou = inter / (ai + aj - inter);
        if (iou > NMS_T) bits |= (1u << jj);
    }
    g_mask[(b*PRE_K + i)*MASKW + cbk] = bits;
}

// ---------------- sequential greedy scan + emit ----------------
__global__ void final_kernel(float* __restrict__ out)
{
    const int b = blockIdx.x;
    if (threadIdx.x != 0) return;
    unsigned remv[MASKW];
#pragma unroll
    for (int w = 0; w < MASKW; w++) remv[w] = 0u;
    int nk = 0;
    for (int i = 0; i < PRE_K; i++) {
        if (!((remv[i >> 5] >> (i & 31)) & 1u)) {
            const float* bx = &g_boxes[(b*PRE_K + i)*4];
            float* o = &out[(b*POST_K + nk)*4];
            o[0] = bx[0]; o[1] = bx[1]; o[2] = bx[2]; o[3] = bx[3];
            nk++;
            if (nk >= POST_K) break;
            const unsigned* m = &g_mask[(b*PRE_K + i)*MASKW];
#pragma unroll
            for (int w = 0; w < MASKW; w++) remv[w] |= m[w];
        }
    }
    for (int k = nk; k < POST_K; k++) {
        float* o = &out[(b*POST_K + k)*4];
        o[0] = 0.f; o[1] = 0.f; o[2] = 0.f; o[3] = 0.f;
    }
}

// ---------------- launcher ----------------
extern "C" void kernel_launch(void* const* d_in, const int* in_sizes, int n_in,
                              void* d_out, int out_size)
{
    const float* feat = (const float*)d_in[0];
    const float* cw   = (const float*)d_in[1];
    const float* cb   = (const float*)d_in[2];
    const float* clw  = (const float*)d_in[3];
    const float* clb  = (const float*)d_in[4];
    const float* bw   = (const float*)d_in[5];
    const float* bb   = (const float*)d_in[6];
    const int*   ihp  = (const int*)d_in[7];
    const int*   iwp  = (const int*)d_in[8];
    float* out = (float*)d_out;

    static int smem_set = 0;
    if (!smem_set) {
        cudaFuncSetAttribute(conv_tc, cudaFuncAttributeMaxDynamicSharedMemorySize, SM_TOTAL);
        smem_set = 1;
    }

    prep_w<<<2304, 256>>>(cw);
    prep_f<<<16384, 256>>>(feat);
    prep_heads<<<49, 256>>>(clw, clb, bw, bb);
    conv_tc<<<dim3(4, 128, 4), 256, SM_TOTAL>>>(cb);
    heads_kernel<<<BATCH*NPIX/32, 256>>>();
    select_kernel<<<BATCH, 1024>>>();
    decode_kernel<<<BATCH, 640>>>(ihp, iwp);
    nms_mask_kernel<<<dim3(MASKW, MASKW, BATCH), 32>>>();
    final_kernel<<<BATCH, 32>>>(out);
}

// round 12
// speedup vs baseline: 2.1753x; 1.1868x over previous
#include <cuda_runtime.h>
#include <cuda_bf16.h>
#include <cstdint>
#include <math.h>

// ---------------- problem constants ----------------
#define BATCH 4
#define CIN   256
#define HH    128
#define WW    128
#define NANCH 9
#define NPIX  (HH*WW)         // 16384
#define NSC   (NPIX*NANCH)    // 147456 per image
#define PRE_K 600
#define POST_K 100
#define NMS_T 0.7f
#define MASKW 19              // ceil(600/32)

#define FSZ ((size_t)BATCH*NPIX*CIN)     // 16777216 elems per split
#define WSZ ((size_t)256*9*256)          // 589824 elems per split

// ---------------- device scratch (static; no allocations) ----------------
__device__ __align__(16) __nv_bfloat16 g_fs[2*FSZ];               // features NHWC, bf16 x2 splits
__device__ __align__(16) __nv_bfloat16 g_ts[2*FSZ];               // conv out NHWC, bf16 x2 splits
__device__ __align__(16) __nv_bfloat16 g_wb[2*WSZ];               // conv weights [s][oc][tap][ci]
__device__ __align__(16) __nv_bfloat16 g_hwb[2*48*256];           // head weights [s][o][k] bf16
__device__ float g_hb[48];
__device__ __align__(16) float g_anch[NANCH*4];
__device__ __align__(16) float g_scores[BATCH*NSC];
__device__ __align__(16) float g_deltas[(size_t)BATCH*NSC*4];
__device__ unsigned g_h16[BATCH*65536];
__device__ unsigned g_cG[BATCH], g_cE[BATCH], g_T16[BATCH];
__device__ __align__(16) unsigned long long g_candG[BATCH*1024];
__device__ __align__(16) unsigned long long g_candE[BATCH*1024];
__device__ unsigned g_topidx[BATCH*PRE_K];
__device__ __align__(16) float g_boxes[BATCH*PRE_K*4];
__device__ unsigned g_mask[BATCH*PRE_K*MASKW];

// ---------------- small helpers ----------------
__device__ __forceinline__ unsigned okey(float f) {
    unsigned u = __float_as_uint(f);
    return (u & 0x80000000u) ? ~u : (u | 0x80000000u);
}
__device__ __forceinline__ float dimval(const int* p) {
    int raw = *p;
    if (raw > 0 && raw < 1000000) return (float)raw;
    return __int_as_float(raw);
}
__device__ __forceinline__ uint32_t smem_u32(const void* p) {
    uint32_t a;
    asm("{ .reg .u64 t; cvta.to.shared.u64 t, %1; cvt.u32.u64 %0, t; }" : "=r"(a) : "l"(p));
    return a;
}
__device__ __forceinline__ void split2(float v, __nv_bfloat16& h1, __nv_bfloat16& h2) {
    h1 = __float2bfloat16_rn(v);
    h2 = __float2bfloat16_rn(v - __bfloat162float(h1));
}

#define LDMX4(r0,r1,r2,r3,addr) \
    asm volatile("ldmatrix.sync.aligned.m8n8.x4.shared.b16 {%0,%1,%2,%3}, [%4];" \
        : "=r"(r0), "=r"(r1), "=r"(r2), "=r"(r3) : "r"(addr))

#define MMA16816(d,a,b) \
    asm volatile("mma.sync.aligned.m16n8k16.row.col.f32.bf16.bf16.f32 " \
        "{%0,%1,%2,%3}, {%4,%5,%6,%7}, {%8,%9}, {%0,%1,%2,%3};" \
        : "+f"((d)[0]), "+f"((d)[1]), "+f"((d)[2]), "+f"((d)[3]) \
        : "r"((a)[0]), "r"((a)[1]), "r"((a)[2]), "r"((a)[3]), "r"((b)[0]), "r"((b)[1]))

#define CP_ASYNC16(daddr, gptr, sz) \
    asm volatile("cp.async.cg.shared.global [%0], [%1], 16, %2;" \
        :: "r"(daddr), "l"(gptr), "r"(sz))
#define CP_COMMIT() asm volatile("cp.async.commit_group;" ::: "memory")
#define CP_WAIT0()  asm volatile("cp.async.wait_group 0;" ::: "memory")

// ---------------- prep: conv weight split ----------------
__global__ void prep_w(const float* __restrict__ cw)
{
    int e = blockIdx.x * 256 + threadIdx.x;
    if (e >= (int)WSZ) return;
    int oc = e / 2304; int r = e - oc*2304; int tap = r >> 8; int ci = r & 255;
    float v = cw[(oc*256 + ci)*9 + tap];
    __nv_bfloat16 h1, h2; split2(v, h1, h2);
    g_wb[e] = h1; g_wb[WSZ + e] = h2;
}

// ---------------- prep: feature NCHW fp32 -> NHWC bf16 x2 ----------------
__global__ __launch_bounds__(256) void prep_f(const float* __restrict__ feat)
{
    int bid = blockIdx.x;
    int xg = bid & 3; int cg = (bid >> 2) & 7; int y = (bid >> 5) & 127; int b = bid >> 12;
    __shared__ float ts[32][33];
    int tid = threadIdx.x;
#pragma unroll
    for (int i = 0; i < 4; i++) {
        int f = tid + i*256;
        int cc = f >> 5, xx = f & 31;
        ts[cc][xx] = feat[((size_t)((b*256 + cg*32 + cc)*128 + y) << 7) + xg*32 + xx];
    }
    __syncthreads();
#pragma unroll
    for (int i = 0; i < 4; i++) {
        int f = tid + i*256;
        int xx = f >> 5, cc = f & 31;
        float v = ts[cc][xx];
        __nv_bfloat16 h1, h2; split2(v, h1, h2);
        size_t o = ((size_t)((b*128 + y)*128 + xg*32 + xx))*256 + cg*32 + cc;
        g_fs[o] = h1; g_fs[FSZ + o] = h2;
    }
}

// ---------------- prep: head weights (bf16 x2) + bias + anchors ----------------
__global__ void prep_heads(const float* __restrict__ clw, const float* __restrict__ clb,
                           const float* __restrict__ bw,  const float* __restrict__ bb)
{
    int i = blockIdx.x * 256 + threadIdx.x;
    if (i < 48*256) {
        int o = i >> 8; int k = i & 255;
        float v = 0.f;
        if (o < 9) v = clw[o*256 + k];
        else if (o < 45) v = bw[(o-9)*256 + k];
        __nv_bfloat16 h1, h2; split2(v, h1, h2);
        g_hwb[i] = h1; g_hwb[48*256 + i] = h2;
        return;
    }
    i -= 48*256;
    if (i < 48) {
        float v = 0.f;
        if (i < 9) v = clb[i]; else if (i < 45) v = bb[i-9];
        g_hb[i] = v;
        return;
    }
    i -= 48;
    if (i < 36) {
        int a = i >> 2, c = i & 3;
        int si = a / 3, ri = a - si*3;
        double sc = (si == 0) ? 8.0 : (si == 1) ? 16.0 : 32.0;
        double rt = (ri == 0) ? 0.5 : (ri == 1) ? 1.0 : 2.0;
        double w = 16.0 * sc * sqrt(rt);
        double h = 16.0 * sc / sqrt(rt);
        double v = (c == 0) ? (-w*0.5) : (c == 1) ? (-h*0.5) : (c == 2) ? (w*0.5) : (h*0.5);
        g_anch[i] = (float)v;
    }
}

// ---------------- conv 3x3 + bias + relu via mma.sync bf16x2 + cp.async ----------------
#define ROWB   80
#define A_SPL  (128*ROWB)
#define A_SZ   (2*A_SPL)
#define B_SPL  (64*ROWB)
#define B_SZ   (2*B_SPL)
#define STG_SZ (A_SZ + B_SZ)         // 30720
#define SM_TOTAL (2*STG_SZ)          // 61440

extern __shared__ char cv_smem[];

__global__ __launch_bounds__(256, 2) void conv_tc(const float* __restrict__ bias)
{
    char* smem = cv_smem;
    const uint32_t sbase = smem_u32(smem);
    const int tid  = threadIdx.x;
    const int wid  = tid >> 5;
    const int lane = tid & 31;
    const int wm   = wid & 3;
    const int wn   = wid >> 2;
    const int oc0  = blockIdx.x * 64;
    const int y    = blockIdx.y;
    const int b    = blockIdx.z;

    float acc[2][4][4];
#pragma unroll
    for (int mt = 0; mt < 2; mt++)
#pragma unroll
        for (int nt = 0; nt < 4; nt++)
#pragma unroll
            for (int q = 0; q < 4; q++) acc[mt][nt][q] = 0.f;

    auto issue_stage = [&](int kc) {
        const int st = kc & 1;
        const int tap = kc >> 3, ci0 = (kc & 7) << 5;
        const int ky = tap / 3, kx = tap - ky*3;
        const int yy = y + ky - 1;
        const bool vy = ((unsigned)yy < 128u);
#pragma unroll
        for (int i = 0; i < 6; i++) {
            int v = tid + i*256;
            if (v < 1024) {
                int s = v >> 9;
                int r2 = v & 511;
                int row = r2 >> 2;
                int c   = r2 & 3;
                uint32_t daddr = sbase + st*STG_SZ + s*A_SPL + row*ROWB + c*16;
                int xx = row + kx - 1;
                bool ok = vy && ((unsigned)xx < 128u);
                const __nv_bfloat16* gp = ok
                    ? g_fs + (size_t)s*FSZ + ((size_t)((b*128 + yy)*128 + xx))*256 + ci0 + c*8
                    : g_fs;
                CP_ASYNC16(daddr, gp, ok ? 16 : 0);
            } else {
                int r = v - 1024;
                int s = r >> 8;
                int r2 = r & 255;
                int row = r2 >> 2;
                int c   = r2 & 3;
                uint32_t daddr = sbase + st*STG_SZ + A_SZ + s*B_SPL + row*ROWB + c*16;
                const __nv_bfloat16* gp = g_wb + (size_t)s*WSZ + ((size_t)((oc0 + row)*9 + tap))*256 + ci0 + c*8;
                CP_ASYNC16(daddr, gp, 16);
            }
        }
        CP_COMMIT();
    };

    auto compute = [&](int st) {
        const uint32_t abase = sbase + st*STG_SZ;
        const uint32_t bbase = abase + A_SZ;
#pragma unroll
        for (int h = 0; h < 2; h++) {
            uint32_t colo = h*32 + ((lane >> 4) << 4);
            uint32_t afr[2][2][4];
#pragma unroll
            for (int s = 0; s < 2; s++) {
#pragma unroll
                for (int mt = 0; mt < 2; mt++) {
                    uint32_t addr = abase + s*A_SPL + (wm*32 + mt*16 + (lane & 15))*ROWB + colo;
                    LDMX4(afr[s][mt][0], afr[s][mt][1], afr[s][mt][2], afr[s][mt][3], addr);
                }
            }
#pragma unroll
            for (int sb = 0; sb < 2; sb++) {
                uint32_t bfr[4][2];
#pragma unroll
                for (int p = 0; p < 2; p++) {
                    uint32_t r0, r1, r2, r3;
                    uint32_t addr = bbase + sb*B_SPL + (wn*32 + p*16 + (lane & 15))*ROWB + colo;
                    LDMX4(r0, r1, r2, r3, addr);
                    bfr[2*p][0] = r0;   bfr[2*p][1] = r2;
                    bfr[2*p+1][0] = r1; bfr[2*p+1][1] = r3;
                }
                int nA = (sb == 0) ? 2 : 1;
#pragma unroll
                for (int sa = 0; sa < 2; sa++) {
                    if (sa >= nA) break;
#pragma unroll
                    for (int mt = 0; mt < 2; mt++)
#pragma unroll
                        for (int nt = 0; nt < 4; nt++)
                            MMA16816(acc[mt][nt], afr[sa][mt], bfr[nt]);
                }
            }
        }
    };

    const int NCH = 72;
    issue_stage(0);
#pragma unroll 1
    for (int c = 0; c < NCH; c++) {
        CP_WAIT0();
        __syncthreads();
        if (c + 1 < NCH) issue_stage(c + 1);
        compute(c & 1);
    }

    // epilogue: bias + relu -> bf16x2 split planes (consumed by heads_mma)
    const int gid = lane >> 2, tg = lane & 3;
#pragma unroll
    for (int mt = 0; mt < 2; mt++) {
#pragma unroll
        for (int nt = 0; nt < 4; nt++) {
            int col = oc0 + wn*32 + nt*8 + tg*2;
            float b0 = __ldg(&bias[col]);
            float b1 = __ldg(&bias[col + 1]);
#pragma unroll
            for (int hf = 0; hf < 2; hf++) {
                float vx = fmaxf(acc[mt][nt][hf*2+0] + b0, 0.f);
                float vy = fmaxf(acc[mt][nt][hf*2+1] + b1, 0.f);
                __nv_bfloat16 x1, x2, y1, y2;
                split2(vx, x1, x2); split2(vy, y1, y2);
                size_t base = ((size_t)((b*128 + y)*128 + wm*32 + mt*16 + gid + hf*8))*256 + col;
                __nv_bfloat162 p0; p0.x = x1; p0.y = y1;
                __nv_bfloat162 p1; p1.x = x2; p1.y = y2;
                *(__nv_bfloat162*)(g_ts + base)       = p0;
                *(__nv_bfloat162*)(g_ts + FSZ + base) = p1;
            }
        }
    }
}

// ---------------- heads via mma.sync bf16x2 (M=65536, N=48, K=256) ----------------
#define HA_ROWB 144
#define HA_SPL  (128*HA_ROWB)        // 18432
#define HA_STG  (2*HA_SPL)           // 36864
#define HB_ROWB 528
#define HB_SPL  (48*HB_ROWB)         // 25344
#define HB_OFF  (2*HA_STG)           // 73728
#define H_TOTAL (HB_OFF + 2*HB_SPL)  // 124416

__global__ __launch_bounds__(256) void heads_mma()
{
    char* smem = cv_smem;
    const uint32_t sbase = smem_u32(smem);
    const int tid  = threadIdx.x;
    const int wm   = tid >> 5;       // warp = m16 tile
    const int lane = tid & 31;
    const int px0  = blockIdx.x * 128;

    float acc[6][4];
#pragma unroll
    for (int nt = 0; nt < 6; nt++)
#pragma unroll
        for (int q = 0; q < 4; q++) acc[nt][q] = 0.f;

    // load B (head weights, both splits): 48 rows x 512B x2 = 3072 x 16B
#pragma unroll
    for (int i = 0; i < 12; i++) {
        int v = tid + i*256;
        int s = v >= 1536; int r = s ? v - 1536 : v;
        int row = r >> 5, c = r & 31;
        uint32_t daddr = sbase + HB_OFF + s*HB_SPL + row*HB_ROWB + c*16;
        const __nv_bfloat16* gp = g_hwb + (size_t)s*48*256 + row*256 + c*8;
        CP_ASYNC16(daddr, gp, 16);
    }
    CP_COMMIT();

    auto issue_a = [&](int kc) {
        const int st = kc & 1;
#pragma unroll
        for (int i = 0; i < 8; i++) {
            int v = tid + i*256;              // 0..2047
            int s = v >= 1024; int r = v & 1023;
            int row = r >> 3, c = r & 7;
            uint32_t daddr = sbase + st*HA_STG + s*HA_SPL + row*HA_ROWB + c*16;
            const __nv_bfloat16* gp = g_ts + (size_t)s*FSZ + ((size_t)(px0 + row))*256 + kc*64 + c*8;
            CP_ASYNC16(daddr, gp, 16);
        }
        CP_COMMIT();
    };

    issue_a(0);
#pragma unroll 1
    for (int kc = 0; kc < 4; kc++) {
        CP_WAIT0();
        __syncthreads();
        if (kc + 1 < 4) issue_a(kc + 1);
        const int st = kc & 1;
#pragma unroll
        for (int h = 0; h < 4; h++) {
            uint32_t colo = h*32 + ((lane >> 4) << 4);
            uint32_t afr[2][4];
#pragma unroll
            for (int s = 0; s < 2; s++) {
                uint32_t addr = sbase + st*HA_STG + s*HA_SPL + (wm*16 + (lane & 15))*HA_ROWB + colo;
                LDMX4(afr[s][0], afr[s][1], afr[s][2], afr[s][3], addr);
            }
            uint32_t bcol = kc*128 + h*32 + ((lane >> 4) << 4);
            uint32_t bfr[2][6][2];
#pragma unroll
            for (int s = 0; s < 2; s++) {
#pragma unroll
                for (int p = 0; p < 3; p++) {
                    uint32_t r0, r1, r2, r3;
                    uint32_t addr = sbase + HB_OFF + s*HB_SPL + (p*16 + (lane & 15))*HB_ROWB + bcol;
                    LDMX4(r0, r1, r2, r3, addr);
                    bfr[s][2*p][0] = r0;   bfr[s][2*p][1] = r2;
                    bfr[s][2*p+1][0] = r1; bfr[s][2*p+1][1] = r3;
                }
            }
#pragma unroll
            for (int nt = 0; nt < 6; nt++) {
                MMA16816(acc[nt], afr[0], bfr[0][nt]);   // a1*b1
                MMA16816(acc[nt], afr[0], bfr[1][nt]);   // a1*b2
                MMA16816(acc[nt], afr[1], bfr[0][nt]);   // a2*b1
            }
        }
        __syncthreads();
    }

    // epilogue: bias, scatter to scores/deltas
    const int gid = lane >> 2, tg = lane & 3;
#pragma unroll
    for (int nt = 0; nt < 6; nt++) {
#pragma unroll
        for (int hf = 0; hf < 2; hf++) {
            int px = px0 + wm*16 + gid + hf*8;
            int b  = px >> 14;
            int pxi = px & 16383;
#pragma unroll
            for (int e = 0; e < 2; e++) {
                int o = nt*8 + tg*2 + e;
                float v = acc[nt][hf*2 + e] + g_hb[o];
                if (o < 9) {
                    g_scores[(size_t)b*NSC + pxi*9 + o] = v;
                } else if (o < 45) {
                    int q = o - 9;
                    g_deltas[((size_t)b*NSC + pxi*9 + (q >> 2))*4 + (q & 3)] = v;
                }
            }
        }
    }
}

// ---------------- select: global 16-bit histogram + threshold + collect + sort ----------------
__global__ void sel_zero()
{
    int i = blockIdx.x * 1024 + threadIdx.x;
    g_h16[i] = 0u;
    if (blockIdx.x == 0 && threadIdx.x < BATCH) {
        g_cG[threadIdx.x] = 0u; g_cE[threadIdx.x] = 0u;
    }
}

__global__ __launch_bounds__(512) void sel_hist()
{
    const int b = blockIdx.y;
    const float4* sc4 = (const float4*)(g_scores + (size_t)b*NSC);
    int idx = blockIdx.x*512 + threadIdx.x;          // 72*512 = 36864 float4
    float4 v = sc4[idx];
    unsigned* hb = g_h16 + b*65536;
    atomicAdd(&hb[okey(v.x) >> 16], 1u);
    atomicAdd(&hb[okey(v.y) >> 16], 1u);
    atomicAdd(&hb[okey(v.z) >> 16], 1u);
    atomicAdd(&hb[okey(v.w) >> 16], 1u);
}

__global__ __launch_bounds__(1024) void sel_scan()
{
    const int b = blockIdx.x;
    const int tid = threadIdx.x;
    __shared__ unsigned part[1024];
    unsigned local = 0;
    const unsigned* hb = g_h16 + b*65536 + tid*64;
#pragma unroll 8
    for (int j = 0; j < 64; j++) local += hb[j];
    part[tid] = local;
    __syncthreads();
    if (tid == 0) {
        unsigned cum = 0; int tt = 1023;
        for (; tt >= 0; tt--) {
            if (cum + part[tt] >= PRE_K) break;
            cum += part[tt];
        }
        const unsigned* hbb = g_h16 + b*65536 + tt*64;
        unsigned c2 = cum; int binT = tt*64;
        for (int j = 63; j >= 0; j--) {
            unsigned h = hbb[j];
            if (c2 + h >= PRE_K) { binT = tt*64 + j; break; }
            c2 += h;
        }
        g_T16[b] = (unsigned)binT;
    }
}

__global__ __launch_bounds__(512) void sel_collect()
{
    const int b = blockIdx.y;
    const unsigned T = g_T16[b];
    const float4* sc4 = (const float4*)(g_scores + (size_t)b*NSC);
    int idx = blockIdx.x*512 + threadIdx.x;
    float4 v = sc4[idx];
    float va[4] = {v.x, v.y, v.z, v.w};
#pragma unroll
    for (int e = 0; e < 4; e++) {
        unsigned n = (unsigned)(idx*4 + e);
        unsigned k = okey(va[e]);
        unsigned hi = k >> 16;
        unsigned long long pk = (((unsigned long long)k) << 32) | (unsigned long long)(0xFFFFFFFFu - n);
        if (hi > T) {
            unsigned pos = atomicAdd(&g_cG[b], 1u);
            if (pos < 1024u) g_candG[b*1024 + pos] = pk;
        } else if (hi == T) {
            unsigned pos = atomicAdd(&g_cE[b], 1u);
            if (pos < 1024u) g_candE[b*1024 + pos] = pk;
        }
    }
}

__global__ __launch_bounds__(1024) void sel_final()
{
    const int b = blockIdx.x;
    const int tid = threadIdx.x;
    __shared__ unsigned long long val[2048];
    unsigned nG = g_cG[b]; if (nG > 1024u) nG = 1024u;
    unsigned nE = g_cE[b]; if (nE > 1024u) nE = 1024u;
    val[tid]        = (tid < (int)nG) ? g_candG[b*1024 + tid] : 0ull;
    val[1024 + tid] = (tid < (int)nE) ? g_candE[b*1024 + tid] : 0ull;
    __syncthreads();
    for (int k = 2; k <= 2048; k <<= 1) {
        for (int j = k >> 1; j > 0; j >>= 1) {
#pragma unroll
            for (int e = 0; e < 2; e++) {
                int i = tid + e*1024;
                int ixj = i ^ j;
                if (ixj > i) {
                    unsigned long long a = val[i], c = val[ixj];
                    bool descBlock = ((i & k) == 0);
                    if ((a < c) == descBlock) { val[i] = c; val[ixj] = a; }
                }
            }
            __syncthreads();
        }
    }
    if (tid < PRE_K)
        g_topidx[b*PRE_K + tid] = 0xFFFFFFFFu - (unsigned)(val[tid] & 0xFFFFFFFFull);
}

// ---------------- decode + clip ----------------
__global__ void decode_kernel(const int* ihp, const int* iwp)
{
    const int b = blockIdx.x, j = threadIdx.x;
    if (j >= PRE_K) return;
    const float img_h = dimval(ihp);
    const float img_w = dimval(iwp);

    unsigned n = g_topidx[b*PRE_K + j];
    int a  = n % 9;
    int px = n / 9;
    int x  = px & 127, y = px >> 7;
    float sx = x * 16.0f, sy = y * 16.0f;

    float b0 = g_anch[a*4+0], b1 = g_anch[a*4+1], b2 = g_anch[a*4+2], b3 = g_anch[a*4+3];
    float ax1 = b0 + sx, ay1 = b1 + sy, ax2 = b2 + sx, ay2 = b3 + sy;
    float w = ax2 - ax1, h = ay2 - ay1;
    float cx = ax1 + 0.5f*w, cy = ay1 + 0.5f*h;

    const float* d = &g_deltas[((size_t)b*NSC + n)*4];
    float dx = d[0], dy = d[1], dw = d[2], dh = d[3];
    float pcx = cx + dx*w, pcy = cy + dy*h;
    float pw = w * expf(dw), ph = h * expf(dh);
    float x1 = pcx - 0.5f*pw, y1 = pcy - 0.5f*ph;
    float x2 = pcx + 0.5f*pw, y2 = pcy + 0.5f*ph;
    x1 = fminf(fmaxf(x1, 0.f), img_w);
    y1 = fminf(fmaxf(y1, 0.f), img_h);
    x2 = fminf(fmaxf(x2, 0.f), img_w);
    y2 = fminf(fmaxf(y2, 0.f), img_h);

    float* ob = &g_boxes[(b*PRE_K + j)*4];
    ob[0] = x1; ob[1] = y1; ob[2] = x2; ob[3] = y2;
}

// ---------------- NMS suppression bitmask ----------------
__global__ void nms_mask_kernel()
{
    const int b = blockIdx.z, cbk = blockIdx.x, rbk = blockIdx.y, t = threadIdx.x;
    __shared__ float4 colb[32];
    int j = cbk*32 + t;
    if (j < PRE_K) colb[t] = *(const float4*)&g_boxes[(b*PRE_K + j)*4];
    __syncthreads();

    int i = rbk*32 + t;
    if (i >= PRE_K) return;
    float4 bi = *(const float4*)&g_boxes[(b*PRE_K + i)*4];
    float ai = (bi.z - bi.x) * (bi.w - bi.y);
    unsigned bits = 0u;
#pragma unroll
    for (int jj = 0; jj < 32; jj++) {
        int jg = cbk*32 + jj;
        if (jg >= PRE_K) break;
        if (jg <= i) continue;
        float4 bj = colb[jj];
        float xx1 = fmaxf(bi.x, bj.x), yy1 = fmaxf(bi.y, bj.y);
        float xx2 = fminf(bi.z, bj.z), yy2 = fminf(bi.w, bj.w);
        float inter = fmaxf(xx2 - xx1, 0.f) * fmaxf(yy2 - yy1, 0.f);
        float aj = (bj.z - bj.x) * (bj.w - bj.y);
        float iou = inter / (ai + aj - inter);
        if (iou > NMS_T) bits |= (1u << jj);
    }
    g_mask[(b*PRE_K + i)*MASKW + cbk] = bits;
}

// ---------------- sequential greedy scan + emit ----------------
__global__ void final_kernel(float* __restrict__ out)
{
    const int b = blockIdx.x;
    if (threadIdx.x != 0) return;
    unsigned remv[MASKW];
#pragma unroll
    for (int w = 0; w < MASKW; w++) remv[w] = 0u;
    int nk = 0;
    for (int i = 0; i < PRE_K; i++) {
        if (!((remv[i >> 5] >> (i & 31)) & 1u)) {
            const float* bx = &g_boxes[(b*PRE_K + i)*4];
            float* o = &out[(b*POST_K + nk)*4];
            o[0] = bx[0]; o[1] = bx[1]; o[2] = bx[2]; o[3] = bx[3];
            nk++;
            if (nk >= POST_K) break;
            const unsigned* m = &g_mask[(b*PRE_K + i)*MASKW];
#pragma unroll
            for (int w = 0; w < MASKW; w++) remv[w] |= m[w];
        }
    }
    for (int k = nk; k < POST_K; k++) {
        float* o = &out[(b*POST_K + k)*4];
        o[0] = 0.f; o[1] = 0.f; o[2] = 0.f; o[3] = 0.f;
    }
}

// ---------------- launcher ----------------
extern "C" void kernel_launch(void* const* d_in, const int* in_sizes, int n_in,
                              void* d_out, int out_size)
{
    const float* feat = (const float*)d_in[0];
    const float* cw   = (const float*)d_in[1];
    const float* cb   = (const float*)d_in[2];
    const float* clw  = (const float*)d_in[3];
    const float* clb  = (const float*)d_in[4];
    const float* bw   = (const float*)d_in[5];
    const float* bb   = (const float*)d_in[6];
    const int*   ihp  = (const int*)d_in[7];
    const int*   iwp  = (const int*)d_in[8];
    float* out = (float*)d_out;

    static int smem_set = 0;
    if (!smem_set) {
        cudaFuncSetAttribute(conv_tc,   cudaFuncAttributeMaxDynamicSharedMemorySize, SM_TOTAL);
        cudaFuncSetAttribute(heads_mma, cudaFuncAttributeMaxDynamicSharedMemorySize, H_TOTAL);
        smem_set = 1;
    }

    prep_w<<<2304, 256>>>(cw);
    prep_f<<<16384, 256>>>(feat);
    prep_heads<<<49, 256>>>(clw, clb, bw, bb);
    sel_zero<<<256, 1024>>>();
    conv_tc<<<dim3(4, 128, 4), 256, SM_TOTAL>>>(cb);
    heads_mma<<<512, 256, H_TOTAL>>>();
    sel_hist<<<dim3(72, BATCH), 512>>>();
    sel_scan<<<BATCH, 1024>>>();
    sel_collect<<<dim3(72, BATCH), 512>>>();
    sel_final<<<BATCH, 1024>>>();
    decode_kernel<<<BATCH, 640>>>(ihp, iwp);
    nms_mask_kernel<<<dim3(MASKW, MASKW, BATCH), 32>>>();
    final_kernel<<<BATCH, 32>>>(out);
}

// round 13
// speedup vs baseline: 2.1868x; 1.0053x over previous
#include <cuda_runtime.h>
#include <cuda_bf16.h>
#include <cstdint>
#include <math.h>

// ---------------- problem constants ----------------
#define BATCH 4
#define CIN   256
#define HH    128
#define WW    128
#define NANCH 9
#define NPIX  (HH*WW)         // 16384
#define NSC   (NPIX*NANCH)    // 147456 per image
#define PRE_K 600
#define POST_K 100
#define NMS_T 0.7f
#define MASKW 19              // ceil(600/32)

#define FSZ ((size_t)BATCH*NPIX*CIN)     // 16777216 elems per split
#define WSZ ((size_t)256*9*256)          // 589824 elems per split

// ---------------- device scratch (static; no allocations) ----------------
__device__ __align__(16) __nv_bfloat16 g_fs[2*FSZ];               // features NHWC, bf16 x2 splits
__device__ __align__(16) __nv_bfloat16 g_ts[2*FSZ];               // conv out NHWC, bf16 x2 splits
__device__ __align__(16) __nv_bfloat16 g_wb[2*WSZ];               // conv weights [s][oc][tap][ci]
__device__ __align__(16) __nv_bfloat16 g_hwb[2*48*256];           // head weights [s][o][k] bf16
__device__ float g_hb[48];
__device__ __align__(16) float g_anch[NANCH*4];
__device__ __align__(16) float g_scores[BATCH*NSC];
__device__ __align__(16) float g_deltas[(size_t)BATCH*NSC*4];
__device__ unsigned g_h16[BATCH*65536];
__device__ unsigned g_cG[BATCH], g_cE[BATCH], g_T16[BATCH];
__device__ __align__(16) unsigned long long g_candG[BATCH*1024];
__device__ __align__(16) unsigned long long g_candE[BATCH*1024];
__device__ __align__(16) float g_boxes[BATCH*PRE_K*4];
__device__ unsigned g_mask[BATCH*PRE_K*MASKW];

// ---------------- small helpers ----------------
__device__ __forceinline__ unsigned okey(float f) {
    unsigned u = __float_as_uint(f);
    return (u & 0x80000000u) ? ~u : (u | 0x80000000u);
}
__device__ __forceinline__ float dimval(const int* p) {
    int raw = *p;
    if (raw > 0 && raw < 1000000) return (float)raw;
    return __int_as_float(raw);
}
__device__ __forceinline__ uint32_t smem_u32(const void* p) {
    uint32_t a;
    asm("{ .reg .u64 t; cvta.to.shared.u64 t, %1; cvt.u32.u64 %0, t; }" : "=r"(a) : "l"(p));
    return a;
}
__device__ __forceinline__ void split2(float v, __nv_bfloat16& h1, __nv_bfloat16& h2) {
    h1 = __float2bfloat16_rn(v);
    h2 = __float2bfloat16_rn(v - __bfloat162float(h1));
}

#define LDMX4(r0,r1,r2,r3,addr) \
    asm volatile("ldmatrix.sync.aligned.m8n8.x4.shared.b16 {%0,%1,%2,%3}, [%4];" \
        : "=r"(r0), "=r"(r1), "=r"(r2), "=r"(r3) : "r"(addr))

#define MMA16816(d,a,b) \
    asm volatile("mma.sync.aligned.m16n8k16.row.col.f32.bf16.bf16.f32 " \
        "{%0,%1,%2,%3}, {%4,%5,%6,%7}, {%8,%9}, {%0,%1,%2,%3};" \
        : "+f"((d)[0]), "+f"((d)[1]), "+f"((d)[2]), "+f"((d)[3]) \
        : "r"((a)[0]), "r"((a)[1]), "r"((a)[2]), "r"((a)[3]), "r"((b)[0]), "r"((b)[1]))

#define CP_ASYNC16(daddr, gptr, sz) \
    asm volatile("cp.async.cg.shared.global [%0], [%1], 16, %2;" \
        :: "r"(daddr), "l"(gptr), "r"(sz))
#define CP_COMMIT() asm volatile("cp.async.commit_group;" ::: "memory")
#define CP_WAIT0()  asm volatile("cp.async.wait_group 0;" ::: "memory")

// ---------------- prep: conv weights + head weights + bias + anchors ----------------
__global__ void prep_wh(const float* __restrict__ cw,
                        const float* __restrict__ clw, const float* __restrict__ clb,
                        const float* __restrict__ bw,  const float* __restrict__ bb)
{
    int i = blockIdx.x * 256 + threadIdx.x;
    if (i < (int)WSZ) {
        int oc = i / 2304; int r = i - oc*2304; int tap = r >> 8; int ci = r & 255;
        float v = cw[(oc*256 + ci)*9 + tap];
        __nv_bfloat16 h1, h2; split2(v, h1, h2);
        g_wb[i] = h1; g_wb[WSZ + i] = h2;
        return;
    }
    i -= (int)WSZ;
    if (i < 48*256) {
        int o = i >> 8; int k = i & 255;
        float v = 0.f;
        if (o < 9) v = clw[o*256 + k];
        else if (o < 45) v = bw[(o-9)*256 + k];
        __nv_bfloat16 h1, h2; split2(v, h1, h2);
        g_hwb[i] = h1; g_hwb[48*256 + i] = h2;
        return;
    }
    i -= 48*256;
    if (i < 48) {
        float v = 0.f;
        if (i < 9) v = clb[i]; else if (i < 45) v = bb[i-9];
        g_hb[i] = v;
        return;
    }
    i -= 48;
    if (i < 36) {
        int a = i >> 2, c = i & 3;
        int si = a / 3, ri = a - si*3;
        double sc = (si == 0) ? 8.0 : (si == 1) ? 16.0 : 32.0;
        double rt = (ri == 0) ? 0.5 : (ri == 1) ? 1.0 : 2.0;
        double w = 16.0 * sc * sqrt(rt);
        double h = 16.0 * sc / sqrt(rt);
        double v = (c == 0) ? (-w*0.5) : (c == 1) ? (-h*0.5) : (c == 2) ? (w*0.5) : (h*0.5);
        g_anch[i] = (float)v;
    }
}

// ---------------- prep: feature NCHW fp32 -> NHWC bf16 x2 (vectorized stores) ----------------
__global__ __launch_bounds__(256) void prep_f(const float* __restrict__ feat)
{
    int bid = blockIdx.x;
    int xg = bid & 3; int cg = (bid >> 2) & 7; int y = (bid >> 5) & 127; int b = bid >> 12;
    __shared__ float ts[32][33];
    int tid = threadIdx.x;
#pragma unroll
    for (int i = 0; i < 4; i++) {
        int f = tid + i*256;
        int cc = f >> 5, xx = f & 31;
        ts[cc][xx] = feat[((size_t)((b*256 + cg*32 + cc)*128 + y) << 7) + xg*32 + xx];
    }
    __syncthreads();
#pragma unroll
    for (int i = 0; i < 2; i++) {
        int f2 = tid + i*256;            // 0..511, each handles 2 channels
        int xx = f2 >> 4;                // 0..31
        int cp = (f2 & 15) * 2;          // 0,2,..,30
        float v0 = ts[cp][xx], v1 = ts[cp+1][xx];
        __nv_bfloat16 a1, a2, b1, b2;
        split2(v0, a1, a2); split2(v1, b1, b2);
        size_t o = ((size_t)((b*128 + y)*128 + xg*32 + xx))*256 + cg*32 + cp;
        __nv_bfloat162 p0; p0.x = a1; p0.y = b1;
        __nv_bfloat162 p1; p1.x = a2; p1.y = b2;
        *(__nv_bfloat162*)(g_fs + o)       = p0;
        *(__nv_bfloat162*)(g_fs + FSZ + o) = p1;
    }
}

// ---------------- conv 3x3 + bias + relu via mma.sync bf16x2 + cp.async ----------------
#define ROWB   80
#define A_SPL  (128*ROWB)
#define A_SZ   (2*A_SPL)
#define B_SPL  (64*ROWB)
#define B_SZ   (2*B_SPL)
#define STG_SZ (A_SZ + B_SZ)         // 30720
#define SM_TOTAL (2*STG_SZ)          // 61440

extern __shared__ char cv_smem[];

__global__ __launch_bounds__(256, 2) void conv_tc(const float* __restrict__ bias)
{
    char* smem = cv_smem;
    const uint32_t sbase = smem_u32(smem);
    const int tid  = threadIdx.x;
    const int wid  = tid >> 5;
    const int lane = tid & 31;
    const int wm   = wid & 3;
    const int wn   = wid >> 2;
    const int oc0  = blockIdx.x * 64;
    const int y    = blockIdx.y;
    const int b    = blockIdx.z;

    float acc[2][4][4];
#pragma unroll
    for (int mt = 0; mt < 2; mt++)
#pragma unroll
        for (int nt = 0; nt < 4; nt++)
#pragma unroll
            for (int q = 0; q < 4; q++) acc[mt][nt][q] = 0.f;

    auto issue_stage = [&](int kc) {
        const int st = kc & 1;
        const int tap = kc >> 3, ci0 = (kc & 7) << 5;
        const int ky = tap / 3, kx = tap - ky*3;
        const int yy = y + ky - 1;
        const bool vy = ((unsigned)yy < 128u);
#pragma unroll
        for (int i = 0; i < 6; i++) {
            int v = tid + i*256;
            if (v < 1024) {
                int s = v >> 9;
                int r2 = v & 511;
                int row = r2 >> 2;
                int c   = r2 & 3;
                uint32_t daddr = sbase + st*STG_SZ + s*A_SPL + row*ROWB + c*16;
                int xx = row + kx - 1;
                bool ok = vy && ((unsigned)xx < 128u);
                const __nv_bfloat16* gp = ok
                    ? g_fs + (size_t)s*FSZ + ((size_t)((b*128 + yy)*128 + xx))*256 + ci0 + c*8
                    : g_fs;
                CP_ASYNC16(daddr, gp, ok ? 16 : 0);
            } else {
                int r = v - 1024;
                int s = r >> 8;
                int r2 = r & 255;
                int row = r2 >> 2;
                int c   = r2 & 3;
                uint32_t daddr = sbase + st*STG_SZ + A_SZ + s*B_SPL + row*ROWB + c*16;
                const __nv_bfloat16* gp = g_wb + (size_t)s*WSZ + ((size_t)((oc0 + row)*9 + tap))*256 + ci0 + c*8;
                CP_ASYNC16(daddr, gp, 16);
            }
        }
        CP_COMMIT();
    };

    auto compute = [&](int st) {
        const uint32_t abase = sbase + st*STG_SZ;
        const uint32_t bbase = abase + A_SZ;
#pragma unroll
        for (int h = 0; h < 2; h++) {
            uint32_t colo = h*32 + ((lane >> 4) << 4);
            uint32_t afr[2][2][4];
#pragma unroll
            for (int s = 0; s < 2; s++) {
#pragma unroll
                for (int mt = 0; mt < 2; mt++) {
                    uint32_t addr = abase + s*A_SPL + (wm*32 + mt*16 + (lane & 15))*ROWB + colo;
                    LDMX4(afr[s][mt][0], afr[s][mt][1], afr[s][mt][2], afr[s][mt][3], addr);
                }
            }
#pragma unroll
            for (int sb = 0; sb < 2; sb++) {
                uint32_t bfr[4][2];
#pragma unroll
                for (int p = 0; p < 2; p++) {
                    uint32_t r0, r1, r2, r3;
                    uint32_t addr = bbase + sb*B_SPL + (wn*32 + p*16 + (lane & 15))*ROWB + colo;
                    LDMX4(r0, r1, r2, r3, addr);
                    bfr[2*p][0] = r0;   bfr[2*p][1] = r2;
                    bfr[2*p+1][0] = r1; bfr[2*p+1][1] = r3;
                }
                int nA = (sb == 0) ? 2 : 1;
#pragma unroll
                for (int sa = 0; sa < 2; sa++) {
                    if (sa >= nA) break;
#pragma unroll
                    for (int mt = 0; mt < 2; mt++)
#pragma unroll
                        for (int nt = 0; nt < 4; nt++)
                            MMA16816(acc[mt][nt], afr[sa][mt], bfr[nt]);
                }
            }
        }
    };

    const int NCH = 72;
    issue_stage(0);
#pragma unroll 1
    for (int c = 0; c < NCH; c++) {
        CP_WAIT0();
        __syncthreads();
        if (c + 1 < NCH) issue_stage(c + 1);
        compute(c & 1);
    }

    // epilogue: bias + relu -> bf16x2 split planes (consumed by heads_mma)
    const int gid = lane >> 2, tg = lane & 3;
#pragma unroll
    for (int mt = 0; mt < 2; mt++) {
#pragma unroll
        for (int nt = 0; nt < 4; nt++) {
            int col = oc0 + wn*32 + nt*8 + tg*2;
            float b0 = __ldg(&bias[col]);
            float b1 = __ldg(&bias[col + 1]);
#pragma unroll
            for (int hf = 0; hf < 2; hf++) {
                float vx = fmaxf(acc[mt][nt][hf*2+0] + b0, 0.f);
                float vy = fmaxf(acc[mt][nt][hf*2+1] + b1, 0.f);
                __nv_bfloat16 x1, x2, y1, y2;
                split2(vx, x1, x2); split2(vy, y1, y2);
                size_t base = ((size_t)((b*128 + y)*128 + wm*32 + mt*16 + gid + hf*8))*256 + col;
                __nv_bfloat162 p0; p0.x = x1; p0.y = y1;
                __nv_bfloat162 p1; p1.x = x2; p1.y = y2;
                *(__nv_bfloat162*)(g_ts + base)       = p0;
                *(__nv_bfloat162*)(g_ts + FSZ + base) = p1;
            }
        }
    }
}

// ---------------- heads via mma.sync bf16x2 (M=65536, N=48, K=256) ----------------
#define HA_ROWB 144
#define HA_SPL  (128*HA_ROWB)        // 18432
#define HA_STG  (2*HA_SPL)           // 36864
#define HB_ROWB 528
#define HB_SPL  (48*HB_ROWB)         // 25344
#define HB_OFF  (2*HA_STG)           // 73728
#define H_TOTAL (HB_OFF + 2*HB_SPL)  // 124416

__global__ __launch_bounds__(256) void heads_mma()
{
    char* smem = cv_smem;
    const uint32_t sbase = smem_u32(smem);
    const int tid  = threadIdx.x;
    const int wm   = tid >> 5;
    const int lane = tid & 31;
    const int px0  = blockIdx.x * 128;

    float acc[6][4];
#pragma unroll
    for (int nt = 0; nt < 6; nt++)
#pragma unroll
        for (int q = 0; q < 4; q++) acc[nt][q] = 0.f;

#pragma unroll
    for (int i = 0; i < 12; i++) {
        int v = tid + i*256;
        int s = v >= 1536; int r = s ? v - 1536 : v;
        int row = r >> 5, c = r & 31;
        uint32_t daddr = sbase + HB_OFF + s*HB_SPL + row*HB_ROWB + c*16;
        const __nv_bfloat16* gp = g_hwb + (size_t)s*48*256 + row*256 + c*8;
        CP_ASYNC16(daddr, gp, 16);
    }
    CP_COMMIT();

    auto issue_a = [&](int kc) {
        const int st = kc & 1;
#pragma unroll
        for (int i = 0; i < 8; i++) {
            int v = tid + i*256;
            int s = v >= 1024; int r = v & 1023;
            int row = r >> 3, c = r & 7;
            uint32_t daddr = sbase + st*HA_STG + s*HA_SPL + row*HA_ROWB + c*16;
            const __nv_bfloat16* gp = g_ts + (size_t)s*FSZ + ((size_t)(px0 + row))*256 + kc*64 + c*8;
            CP_ASYNC16(daddr, gp, 16);
        }
        CP_COMMIT();
    };

    issue_a(0);
#pragma unroll 1
    for (int kc = 0; kc < 4; kc++) {
        CP_WAIT0();
        __syncthreads();
        if (kc + 1 < 4) issue_a(kc + 1);
        const int st = kc & 1;
#pragma unroll
        for (int h = 0; h < 4; h++) {
            uint32_t colo = h*32 + ((lane >> 4) << 4);
            uint32_t afr[2][4];
#pragma unroll
            for (int s = 0; s < 2; s++) {
                uint32_t addr = sbase + st*HA_STG + s*HA_SPL + (wm*16 + (lane & 15))*HA_ROWB + colo;
                LDMX4(afr[s][0], afr[s][1], afr[s][2], afr[s][3], addr);
            }
            uint32_t bcol = kc*128 + h*32 + ((lane >> 4) << 4);
            uint32_t bfr[2][6][2];
#pragma unroll
            for (int s = 0; s < 2; s++) {
#pragma unroll
                for (int p = 0; p < 3; p++) {
                    uint32_t r0, r1, r2, r3;
                    uint32_t addr = sbase + HB_OFF + s*HB_SPL + (p*16 + (lane & 15))*HB_ROWB + bcol;
                    LDMX4(r0, r1, r2, r3, addr);
                    bfr[s][2*p][0] = r0;   bfr[s][2*p][1] = r2;
                    bfr[s][2*p+1][0] = r1; bfr[s][2*p+1][1] = r3;
                }
            }
#pragma unroll
            for (int nt = 0; nt < 6; nt++) {
                MMA16816(acc[nt], afr[0], bfr[0][nt]);
                MMA16816(acc[nt], afr[0], bfr[1][nt]);
                MMA16816(acc[nt], afr[1], bfr[0][nt]);
            }
        }
        __syncthreads();
    }

    const int gid = lane >> 2, tg = lane & 3;
#pragma unroll
    for (int nt = 0; nt < 6; nt++) {
#pragma unroll
        for (int hf = 0; hf < 2; hf++) {
            int px = px0 + wm*16 + gid + hf*8;
            int b  = px >> 14;
            int pxi = px & 16383;
#pragma unroll
            for (int e = 0; e < 2; e++) {
                int o = nt*8 + tg*2 + e;
                float v = acc[nt][hf*2 + e] + g_hb[o];
                if (o < 9) {
                    g_scores[(size_t)b*NSC + pxi*9 + o] = v;
                } else if (o < 45) {
                    int q = o - 9;
                    g_deltas[((size_t)b*NSC + pxi*9 + (q >> 2))*4 + (q & 3)] = v;
                }
            }
        }
    }
}

// ---------------- select ----------------
__global__ __launch_bounds__(512) void sel_hist()
{
    const int b = blockIdx.y;
    const float4* sc4 = (const float4*)(g_scores + (size_t)b*NSC);
    int idx = blockIdx.x*512 + threadIdx.x;
    float4 v = sc4[idx];
    unsigned* hb = g_h16 + b*65536;
    atomicAdd(&hb[okey(v.x) >> 16], 1u);
    atomicAdd(&hb[okey(v.y) >> 16], 1u);
    atomicAdd(&hb[okey(v.z) >> 16], 1u);
    atomicAdd(&hb[okey(v.w) >> 16], 1u);
}

__global__ __launch_bounds__(1024) void sel_scan()
{
    const int b = blockIdx.x;
    const int tid = threadIdx.x;
    __shared__ unsigned part[1024];
    if (tid == 0) { g_cG[b] = 0u; g_cE[b] = 0u; }   // zero counters for sel_collect
    unsigned local = 0;
    const unsigned* hb = g_h16 + b*65536 + tid*64;
#pragma unroll 8
    for (int j = 0; j < 64; j++) local += hb[j];
    part[tid] = local;
    __syncthreads();
    if (tid == 0) {
        unsigned cum = 0; int tt = 1023;
        for (; tt >= 0; tt--) {
            if (cum + part[tt] >= PRE_K) break;
            cum += part[tt];
        }
        const unsigned* hbb = g_h16 + b*65536 + tt*64;
        unsigned c2 = cum; int binT = tt*64;
        for (int j = 63; j >= 0; j--) {
            unsigned h = hbb[j];
            if (c2 + h >= PRE_K) { binT = tt*64 + j; break; }
            c2 += h;
        }
        g_T16[b] = (unsigned)binT;
    }
}

__global__ __launch_bounds__(512) void sel_collect()
{
    const int b = blockIdx.y;
    const unsigned T = g_T16[b];
    const float4* sc4 = (const float4*)(g_scores + (size_t)b*NSC);
    int idx = blockIdx.x*512 + threadIdx.x;
    float4 v = sc4[idx];
    float va[4] = {v.x, v.y, v.z, v.w};
#pragma unroll
    for (int e = 0; e < 4; e++) {
        unsigned n = (unsigned)(idx*4 + e);
        unsigned k = okey(va[e]);
        unsigned hi = k >> 16;
        unsigned long long pk = (((unsigned long long)k) << 32) | (unsigned long long)(0xFFFFFFFFu - n);
        if (hi > T) {
            unsigned pos = atomicAdd(&g_cG[b], 1u);
            if (pos < 1024u) g_candG[b*1024 + pos] = pk;
        } else if (hi == T) {
            unsigned pos = atomicAdd(&g_cE[b], 1u);
            if (pos < 1024u) g_candE[b*1024 + pos] = pk;
        }
    }
    // self-clean the histogram for the next graph replay (sel_scan already consumed it)
    int lin = (b*72 + blockIdx.x)*512 + threadIdx.x;   // 0..147455
#pragma unroll
    for (int z = 0; z < 2; z++) {
        int w = lin*2 + z;
        if (w < BATCH*65536) g_h16[w] = 0u;
    }
}

// sort + decode + clip (merged)
__global__ __launch_bounds__(1024) void sel_final(const int* ihp, const int* iwp)
{
    const int b = blockIdx.x;
    const int tid = threadIdx.x;
    __shared__ unsigned long long val[2048];
    unsigned nG = g_cG[b]; if (nG > 1024u) nG = 1024u;
    unsigned nE = g_cE[b]; if (nE > 1024u) nE = 1024u;
    val[tid]        = (tid < (int)nG) ? g_candG[b*1024 + tid] : 0ull;
    val[1024 + tid] = (tid < (int)nE) ? g_candE[b*1024 + tid] : 0ull;
    __syncthreads();
    for (int k = 2; k <= 2048; k <<= 1) {
        for (int j = k >> 1; j > 0; j >>= 1) {
#pragma unroll
            for (int e = 0; e < 2; e++) {
                int i = tid + e*1024;
                int ixj = i ^ j;
                if (ixj > i) {
                    unsigned long long a = val[i], c = val[ixj];
                    bool descBlock = ((i & k) == 0);
                    if ((a < c) == descBlock) { val[i] = c; val[ixj] = a; }
                }
            }
            __syncthreads();
        }
    }
    if (tid >= PRE_K) return;
    const float img_h = dimval(ihp);
    const float img_w = dimval(iwp);
    unsigned n = 0xFFFFFFFFu - (unsigned)(val[tid] & 0xFFFFFFFFull);
    int a  = n % 9;
    int px = n / 9;
    int x  = px & 127, y = px >> 7;
    float sx = x * 16.0f, sy = y * 16.0f;

    float b0 = g_anch[a*4+0], b1 = g_anch[a*4+1], b2 = g_anch[a*4+2], b3 = g_anch[a*4+3];
    float ax1 = b0 + sx, ay1 = b1 + sy, ax2 = b2 + sx, ay2 = b3 + sy;
    float w = ax2 - ax1, h = ay2 - ay1;
    float cx = ax1 + 0.5f*w, cy = ay1 + 0.5f*h;

    const float* d = &g_deltas[((size_t)b*NSC + n)*4];
    float dx = d[0], dy = d[1], dw = d[2], dh = d[3];
    float pcx = cx + dx*w, pcy = cy + dy*h;
    float pw = w * expf(dw), ph = h * expf(dh);
    float x1 = pcx - 0.5f*pw, y1 = pcy - 0.5f*ph;
    float x2 = pcx + 0.5f*pw, y2 = pcy + 0.5f*ph;
    x1 = fminf(fmaxf(x1, 0.f), img_w);
    y1 = fminf(fmaxf(y1, 0.f), img_h);
    x2 = fminf(fmaxf(x2, 0.f), img_w);
    y2 = fminf(fmaxf(y2, 0.f), img_h);

    float* ob = &g_boxes[(b*PRE_K + tid)*4];
    ob[0] = x1; ob[1] = y1; ob[2] = x2; ob[3] = y2;
}

// ---------------- NMS suppression bitmask ----------------
__global__ void nms_mask_kernel()
{
    const int b = blockIdx.z, cbk = blockIdx.x, rbk = blockIdx.y, t = threadIdx.x;
    __shared__ float4 colb[32];
    int j = cbk*32 + t;
    if (j < PRE_K) colb[t] = *(const float4*)&g_boxes[(b*PRE_K + j)*4];
    __syncthreads();

    int i = rbk*32 + t;
    if (i >= PRE_K) return;
    float4 bi = *(const float4*)&g_boxes[(b*PRE_K + i)*4];
    float ai = (bi.z - bi.x) * (bi.w - bi.y);
    unsigned bits = 0u;
#pragma unroll
    for (int jj = 0; jj < 32; jj++) {
        int jg = cbk*32 + jj;
        if (jg >= PRE_K) break;
        if (jg <= i) continue;
        float4 bj = colb[jj];
        float xx1 = fmaxf(bi.x, bj.x), yy1 = fmaxf(bi.y, bj.y);
        float xx2 = fminf(bi.z, bj.z), yy2 = fminf(bi.w, bj.w);
        float inter = fmaxf(xx2 - xx1, 0.f) * fmaxf(yy2 - yy1, 0.f);
        float aj = (bj.z - bj.x) * (bj.w - bj.y);
        float iou = inter / (ai + aj - inter);
        if (iou > NMS_T) bits |= (1u << jj);
    }
    g_mask[(b*PRE_K + i)*MASKW + cbk] = bits;
}

// ---------------- sequential greedy scan + emit ----------------
__global__ void final_kernel(float* __restrict__ out)
{
    const int b = blockIdx.x;
    if (threadIdx.x != 0) return;
    unsigned remv[MASKW];
#pragma unroll
    for (int w = 0; w < MASKW; w++) remv[w] = 0u;
    int nk = 0;
    for (int i = 0; i < PRE_K; i++) {
        if (!((remv[i >> 5] >> (i & 31)) & 1u)) {
            const float* bx = &g_boxes[(b*PRE_K + i)*4];
            float* o = &out[(b*POST_K + nk)*4];
            o[0] = bx[0]; o[1] = bx[1]; o[2] = bx[2]; o[3] = bx[3];
            nk++;
            if (nk >= POST_K) break;
            const unsigned* m = &g_mask[(b*PRE_K + i)*MASKW];
#pragma unroll
            for (int w = 0; w < MASKW; w++) remv[w] |= m[w];
        }
    }
    for (int k = nk; k < POST_K; k++) {
        float* o = &out[(b*POST_K + k)*4];
        o[0] = 0.f; o[1] = 0.f; o[2] = 0.f; o[3] = 0.f;
    }
}

// ---------------- launcher ----------------
extern "C" void kernel_launch(void* const* d_in, const int* in_sizes, int n_in,
                              void* d_out, int out_size)
{
    const float* feat = (const float*)d_in[0];
    const float* cw   = (const float*)d_in[1];
    const float* cb   = (const float*)d_in[2];
    const float* clw  = (const float*)d_in[3];
    const float* clb  = (const float*)d_in[4];
    const float* bw   = (const float*)d_in[5];
    const float* bb   = (const float*)d_in[6];
    const int*   ihp  = (const int*)d_in[7];
    const int*   iwp  = (const int*)d_in[8];
    float* out = (float*)d_out;

    static int smem_set = 0;
    if (!smem_set) {
        cudaFuncSetAttribute(conv_tc,   cudaFuncAttributeMaxDynamicSharedMemorySize, SM_TOTAL);
        cudaFuncSetAttribute(heads_mma, cudaFuncAttributeMaxDynamicSharedMemorySize, H_TOTAL);
        smem_set = 1;
    }

    prep_wh<<<2353, 256>>>(cw, clw, clb, bw, bb);
    prep_f<<<16384, 256>>>(feat);
    conv_tc<<<dim3(4, 128, 4), 256, SM_TOTAL>>>(cb);
    heads_mma<<<512, 256, H_TOTAL>>>();
    sel_hist<<<dim3(72, BATCH), 512>>>();
    sel_scan<<<BATCH, 1024>>>();
    sel_collect<<<dim3(72, BATCH), 512>>>();
    sel_final<<<BATCH, 1024>>>(ihp, iwp);
    nms_mask_kernel<<<dim3(MASKW, MASKW, BATCH), 32>>>();
    final_kernel<<<BATCH, 32>>>(out);
}